// round 4
// baseline (speedup 1.0000x reference)
#include <cuda_runtime.h>

#define NN 512
#define BB 2
#define DD 128
#define OO 16
#define HH 64
#define CHN 48
#define MROWS 262656
#define TILES 4104
#define H1DIM 514
#define SKIP_OFF (512*512*2*16)

// ---------------- scratch (device globals; no allocation allowed) ----------------
__device__ __align__(16) float g_xc[513*256];
__device__ __align__(16) float g_x2c[513*256];
__device__ __align__(16) float g_x3c[513*256];
__device__ __align__(16) float g_w1T[768*64];
__device__ __align__(16) float g_w2T[64*64];
__device__ __align__(16) float g_w3T[64*16];
__device__ __align__(16) float g_sw1T[384*64];
__device__ __align__(16) float g_sw2T[64*64];
__device__ __align__(16) float g_sw3T[64*16];
__device__ __align__(16) float g_cw1T[16*9*48];
__device__ __align__(16) float g_cw2T[48*9*16];
__device__ __align__(16) float g_A[1024*64];    // x_i . Wseg0 + b1
__device__ __align__(16) float g_Bv[1024*64];   // x_j . Wseg1
__device__ __align__(16) float g_M[1026*64];    // moment cumsum projections
__device__ __align__(16) float g_S[BB*OO*NN*NN];           // conv1 input, NCHW
__device__ __align__(16) float g_H1[BB*CHN*H1DIM*H1DIM];   // conv1 output

__device__ __forceinline__ float gelu(float v){ return v * normcdff(v); }

// ---------------- weight transposes: [O,K] -> [K,O] ----------------
__global__ void k_transpose(const float* __restrict__ src, int which, int Osz, int Ksz){
    float* dst;
    switch(which){
        case 0: dst = g_w1T;  break;
        case 1: dst = g_w2T;  break;
        case 2: dst = g_w3T;  break;
        case 3: dst = g_sw1T; break;
        case 4: dst = g_sw2T; break;
        case 5: dst = g_sw3T; break;
        case 6: dst = g_cw1T; break;
        default: dst = g_cw2T; break;
    }
    int idx = blockIdx.x*blockDim.x + threadIdx.x;
    if (idx < Osz*Ksz){
        int o = idx / Ksz, k = idx - o*Ksz;
        dst[k*Osz + o] = src[idx];
    }
}

// ---------------- prefix sums of moments (513 rows x 256 cols) ----------------
__global__ void k_prefix(const float* __restrict__ x){
    int col = threadIdx.x; // 256 = b*128 + d
    float c1 = 0.f, c2 = 0.f, c3 = 0.f;
    g_xc[col] = 0.f; g_x2c[col] = 0.f; g_x3c[col] = 0.f;
    for (int n = 0; n < NN; n++){
        float v = x[n*256 + col];
        c1 += v; c2 += v*v; c3 += v*v*v;
        g_xc [(n+1)*256 + col] = c1;
        g_x2c[(n+1)*256 + col] = c2;
        g_x3c[(n+1)*256 + col] = c3;
    }
}

// ---------------- separable layer-1 precomputes ----------------
__global__ void k_precompute(const float* __restrict__ x, const float* __restrict__ b1){
    int type = blockIdx.y;      // 0: A, 1: Bv, 2: M
    int rid  = blockIdx.x;
    int t    = threadIdx.x;     // 64 threads, one output channel each
    __shared__ float sIn[384];
    if (type < 2){
        if (rid >= 1024) return;
        const float* xr = x + rid*128;       // rid = i*2 + b
        sIn[t] = xr[t]; sIn[64+t] = xr[64+t];
        __syncthreads();
        float acc = (type == 0) ? b1[t] : 0.f;
        const float* w = g_w1T + (type == 0 ? 0 : 128)*64 + t;
        #pragma unroll 4
        for (int d = 0; d < 128; d++) acc += sIn[d] * w[d*64];
        (type == 0 ? g_A : g_Bv)[rid*64 + t] = acc;
    } else {
        const float* c1 = g_xc  + rid*128;   // rid = r*2 + b, r in [0,512]
        const float* c2 = g_x2c + rid*128;
        const float* c3 = g_x3c + rid*128;
        sIn[t]       = c1[t]; sIn[64+t]  = c1[64+t];
        sIn[128+t]   = c2[t]; sIn[192+t] = c2[64+t];
        sIn[256+t]   = c3[t]; sIn[320+t] = c3[64+t];
        __syncthreads();
        float acc = 0.f;
        #pragma unroll 4
        for (int d = 0; d < 128; d++){
            acc += sIn[d]       * g_w1T[(384+d)*64 + t];
            acc += sIn[128 + d] * g_w1T[(512+d)*64 + t];
            acc += sIn[256 + d] * g_w1T[(640+d)*64 + t];
        }
        g_M[rid*64 + t] = acc;
    }
}

// ---------------- zero dense S (upper triangle must be 0) ----------------
__global__ void k_zero(){
    int idx = blockIdx.x*blockDim.x + threadIdx.x;
    ((float4*)g_S)[idx] = make_float4(0.f, 0.f, 0.f, 0.f);
}

__device__ __forceinline__ void fma16(float acc[4][4], float4 a4, float4 b4){
    acc[0][0] += a4.x*b4.x; acc[0][1] += a4.x*b4.y; acc[0][2] += a4.x*b4.z; acc[0][3] += a4.x*b4.w;
    acc[1][0] += a4.y*b4.x; acc[1][1] += a4.y*b4.y; acc[1][2] += a4.y*b4.z; acc[1][3] += a4.y*b4.w;
    acc[2][0] += a4.z*b4.x; acc[2][1] += a4.z*b4.y; acc[2][2] += a4.z*b4.z; acc[2][3] += a4.z*b4.w;
    acc[3][0] += a4.w*b4.x; acc[3][1] += a4.w*b4.y; acc[3][2] += a4.w*b4.z; acc[3][3] += a4.w*b4.w;
}

// ---------------- pair MLP: 64-row tiles, full 3-layer fused ----------------
__global__ void __launch_bounds__(256) k_pair(const float* __restrict__ x,
                                              const float* __restrict__ b2,
                                              const float* __restrict__ b3){
    __shared__ __align__(16) float sA[64*68];   // [k][row], pad 68
    __shared__ __align__(16) float sB[64*64];   // [k][col]
    __shared__ int   sI[64], sJ[64];
    __shared__ float sInvL[64];

    int tid  = threadIdx.x;
    int base = blockIdx.x * 64;

    if (tid < 64){
        int m = base + tid;
        int p = m >> 1;
        int i = (int)floorf((sqrtf(8.0f*(float)p + 1.0f) - 1.0f) * 0.5f);
        while ((i+1)*(i+2)/2 <= p) i++;
        while (i*(i+1)/2 > p)      i--;
        int j = p - i*(i+1)/2;
        sI[tid] = i; sJ[tid] = j;
        sInvL[tid] = 1.0f / (float)(i - j + 1);
    }
    __syncthreads();

    int tr = tid >> 4, tc = tid & 15;
    float acc[4][4];
    #pragma unroll
    for (int a = 0; a < 4; a++)
        #pragma unroll
        for (int c = 0; c < 4; c++) acc[a][c] = 0.f;

    int row = tid >> 2;
    int dg  = tid & 3;
    int i_r = sI[row], j_r = sJ[row];
    int b_r = (base + row) & 1;
    const float* xi = x + (i_r*2 + b_r)*128 + dg*16;
    const float* xj = x + (j_r*2 + b_r)*128 + dg*16;

    // ---- layer 1: only the curA*curB segment needs a pairwise GEMM (K=128) ----
    for (int kc = 0; kc < 2; kc++){
        int d0 = kc*64;
        #pragma unroll
        for (int q = 0; q < 4; q++){
            float4 a4 = *(const float4*)(xi + d0 + 4*q);
            float4 c4 = *(const float4*)(xj + d0 + 4*q);
            int kk = dg*16 + 4*q;
            sA[(kk+0)*68 + row] = a4.x*c4.x;
            sA[(kk+1)*68 + row] = a4.y*c4.y;
            sA[(kk+2)*68 + row] = a4.z*c4.z;
            sA[(kk+3)*68 + row] = a4.w*c4.w;
        }
        {
            const float4* src = (const float4*)(g_w1T + (256 + d0)*64);
            float4* dst4 = (float4*)sB;
            #pragma unroll
            for (int q = 0; q < 4; q++) dst4[q*256 + tid] = src[q*256 + tid];
        }
        __syncthreads();
        #pragma unroll 8
        for (int kk = 0; kk < 64; kk++){
            float4 a4 = *(const float4*)&sA[kk*68 + tr*4];
            float4 b4 = *(const float4*)&sB[kk*64 + tc*4];
            fma16(acc, a4, b4);
        }
        __syncthreads();
    }

    // ---- add separable precomputes (A[i] + Bv[j] + invL*(M[i+1]-M[j])) via sB ----
    #pragma unroll
    for (int u = 0; u < 16; u++){
        int idx = u*256 + tid;
        int r2 = idx >> 6, oc = idx & 63;
        int ii = sI[r2], jj = sJ[r2];
        int bb = (base + r2) & 1;
        float pre = g_A[(ii*2+bb)*64 + oc] + g_Bv[(jj*2+bb)*64 + oc]
                  + sInvL[r2] * (g_M[((ii+1)*2+bb)*64 + oc] - g_M[(jj*2+bb)*64 + oc]);
        sB[r2*64 + oc] = pre;
    }
    __syncthreads();

    #pragma unroll
    for (int a = 0; a < 4; a++)
        #pragma unroll
        for (int c = 0; c < 4; c++){
            float v = acc[a][c] + sB[(tr*4+a)*64 + tc*4 + c];
            sA[(tc*4+c)*68 + (tr*4+a)] = gelu(v);   // transposed: h1 in [k][row]
            acc[a][c] = 0.f;
        }
    __syncthreads();

    // ---- layer 2 (K=64) ----
    {
        const float4* src = (const float4*)g_w2T;
        float4* dst4 = (float4*)sB;
        #pragma unroll
        for (int q = 0; q < 4; q++) dst4[q*256 + tid] = src[q*256 + tid];
    }
    __syncthreads();
    #pragma unroll 8
    for (int kk = 0; kk < 64; kk++){
        float4 a4 = *(const float4*)&sA[kk*68 + tr*4];
        float4 b4 = *(const float4*)&sB[kk*64 + tc*4];
        fma16(acc, a4, b4);
    }
    __syncthreads();

    float b2v[4];
    #pragma unroll
    for (int c = 0; c < 4; c++) b2v[c] = b2[tc*4 + c];
    #pragma unroll
    for (int a = 0; a < 4; a++)
        #pragma unroll
        for (int c = 0; c < 4; c++)
            sA[(tc*4+c)*68 + (tr*4+a)] = gelu(acc[a][c] + b2v[c]);
    if (tid < 256) ((float4*)sB)[tid] = ((const float4*)g_w3T)[tid];  // 1024 floats
    __syncthreads();

    // ---- layer 3 (64 -> 16) + scatter into NCHW S ----
    int r3 = tid >> 2;
    int og = (tid & 3) * 4;
    float a0 = b3[og], a1 = b3[og+1], a2 = b3[og+2], a3 = b3[og+3];
    #pragma unroll 8
    for (int kk = 0; kk < 64; kk++){
        float av = sA[kk*68 + r3];
        float4 w4 = *(const float4*)&sB[kk*16 + og];
        a0 += av*w4.x; a1 += av*w4.y; a2 += av*w4.z; a3 += av*w4.w;
    }
    int ii = sI[r3], jj = sJ[r3], bb = (base + r3) & 1;
    float* dst = g_S + (((bb*16 + og)*512 + ii)*512 + jj);
    dst[0]           = a0;
    dst[512*512]     = a1;
    dst[2*512*512]   = a2;
    dst[3*512*512]   = a3;
}

// ---------------- conv1: 16->48, 3x3, pad=2, out 514x514, fused GELU ----------------
__global__ void __launch_bounds__(256) k_conv1(const float* __restrict__ cb1){
    __shared__ float sIn[16*18*18];                  // 20736 B
    __shared__ __align__(16) float sW[16*9*48];      // 27648 B
    int b  = blockIdx.z;
    int by = blockIdx.y, bx = blockIdx.x;
    int tid = threadIdx.x;

    for (int idx = tid; idx < 16*9*48/4; idx += 256)
        ((float4*)sW)[idx] = ((const float4*)g_cw1T)[idx];

    int y0 = by*16 - 2, x0 = bx*16 - 2;
    for (int idx = tid; idx < 5184; idx += 256){
        int ic = idx / 324; int rem = idx - ic*324;
        int ly = rem / 18,  lx = rem - ly*18;
        int gy = y0 + ly,   gx = x0 + lx;
        float v = 0.f;
        if ((unsigned)gy < 512u && (unsigned)gx < 512u)
            v = g_S[((b*16 + ic)*512 + gy)*512 + gx];
        sIn[idx] = v;
    }
    __syncthreads();

    int ty = tid >> 4, tx = tid & 15;
    float4 acc[12];
    #pragma unroll
    for (int q = 0; q < 12; q++) acc[q] = make_float4(0.f,0.f,0.f,0.f);

    #pragma unroll 1
    for (int ic = 0; ic < 16; ic++){
        float v[9];
        #pragma unroll
        for (int ky = 0; ky < 3; ky++)
            #pragma unroll
            for (int kx = 0; kx < 3; kx++)
                v[ky*3+kx] = sIn[ic*324 + (ty+ky)*18 + (tx+kx)];
        #pragma unroll
        for (int tap = 0; tap < 9; tap++){
            float vv = v[tap];
            const float4* wp = (const float4*)&sW[(ic*9 + tap)*48];
            #pragma unroll
            for (int q = 0; q < 12; q++){
                float4 w4 = wp[q];
                acc[q].x += vv*w4.x; acc[q].y += vv*w4.y;
                acc[q].z += vv*w4.z; acc[q].w += vv*w4.w;
            }
        }
    }

    int oy = by*16 + ty, ox = bx*16 + tx;
    if (oy < 514 && ox < 514){
        #pragma unroll
        for (int q = 0; q < 12; q++){
            float4 c = *(const float4*)&cb1[q*4];
            float* dst = g_H1 + (((b*48 + q*4)*514 + oy)*514 + ox);
            dst[0]          = gelu(acc[q].x + c.x);
            dst[514*514]    = gelu(acc[q].y + c.y);
            dst[2*514*514]  = gelu(acc[q].z + c.z);
            dst[3*514*514]  = gelu(acc[q].w + c.w);
        }
    }
}

// ---------------- conv2: 48->16, 3x3, valid, + bias + lenBA scale + permute-out ----------------
__global__ void __launch_bounds__(256) k_conv2(const float* __restrict__ cb2,
                                               float* __restrict__ out){
    __shared__ float sIn[16*18*18];
    __shared__ __align__(16) float sW[16*9*16];
    int b  = blockIdx.z;
    int by = blockIdx.y, bx = blockIdx.x;
    int tid = threadIdx.x;
    int ty = tid >> 4, tx = tid & 15;

    float4 acc[4];
    #pragma unroll
    for (int q = 0; q < 4; q++) acc[q] = make_float4(0.f,0.f,0.f,0.f);

    for (int icc = 0; icc < 3; icc++){
        if (icc) __syncthreads();
        for (int idx = tid; idx < 2304/4; idx += 256)
            ((float4*)sW)[idx] = ((const float4*)(g_cw2T + icc*2304))[idx];
        int y0 = by*16, x0 = bx*16;
        for (int idx = tid; idx < 5184; idx += 256){
            int ic = idx / 324; int rem = idx - ic*324;
            int ly = rem / 18,  lx = rem - ly*18;
            sIn[idx] = g_H1[((b*48 + icc*16 + ic)*514 + (y0+ly))*514 + (x0+lx)];
        }
        __syncthreads();
        #pragma unroll 1
        for (int ic = 0; ic < 16; ic++){
            float v[9];
            #pragma unroll
            for (int ky = 0; ky < 3; ky++)
                #pragma unroll
                for (int kx = 0; kx < 3; kx++)
                    v[ky*3+kx] = sIn[ic*324 + (ty+ky)*18 + (tx+kx)];
            #pragma unroll
            for (int tap = 0; tap < 9; tap++){
                float vv = v[tap];
                const float4* wp = (const float4*)&sW[(ic*9 + tap)*16];
                #pragma unroll
                for (int q = 0; q < 4; q++){
                    float4 w4 = wp[q];
                    acc[q].x += vv*w4.x; acc[q].y += vv*w4.y;
                    acc[q].z += vv*w4.z; acc[q].w += vv*w4.w;
                }
            }
        }
    }

    int oy = by*16 + ty, ox = bx*16 + tx;
    int ad = oy - ox; if (ad < 0) ad = -ad; if (ad < 1) ad = 1;
    float scale = (float)ad;
    float* dst = out + ((oy*512 + ox)*2 + b)*16;
    #pragma unroll
    for (int q = 0; q < 4; q++){
        float4 c = ((const float4*)cb2)[q];
        float4 o4;
        o4.x = scale*(acc[q].x + c.x);
        o4.y = scale*(acc[q].y + c.y);
        o4.z = scale*(acc[q].z + c.z);
        o4.w = scale*(acc[q].w + c.w);
        *(float4*)(dst + q*4) = o4;
    }
}

// ---------------- skip MLP on adjacent frames ----------------
__global__ void k_skip(const float* __restrict__ x,  const float* __restrict__ sb1,
                       const float* __restrict__ sb2, const float* __restrict__ sb3,
                       float* __restrict__ out){
    __shared__ float sIn[384], sH[64], sH2[64];
    int bid = blockIdx.x;          // 0..1021
    int tt = bid >> 1, b = bid & 1;
    int t = threadIdx.x;           // 64
    const float* xa = x + (tt*2 + b)*128;
    const float* xb = x + ((tt+1)*2 + b)*128;
    sIn[t]       = xa[t];          sIn[64+t]  = xa[64+t];
    sIn[128+t]   = xb[t];          sIn[192+t] = xb[64+t];
    sIn[256+t]   = xa[t]*xb[t];    sIn[320+t] = xa[64+t]*xb[64+t];
    __syncthreads();
    float acc = sb1[t];
    #pragma unroll 4
    for (int k = 0; k < 384; k++) acc += sIn[k] * g_sw1T[k*64 + t];
    sH[t] = gelu(acc);
    __syncthreads();
    acc = sb2[t];
    #pragma unroll 4
    for (int k = 0; k < 64; k++) acc += sH[k] * g_sw2T[k*64 + t];
    sH2[t] = gelu(acc);
    __syncthreads();
    if (t < 16){
        float a = sb3[t];
        #pragma unroll 4
        for (int k = 0; k < 64; k++) a += sH2[k] * g_sw3T[k*16 + t];
        out[SKIP_OFF + (tt*2 + b)*16 + t] = a;
    }
}

// ---------------- launch ----------------
extern "C" void kernel_launch(void* const* d_in, const int* in_sizes, int n_in,
                              void* d_out, int out_size){
    const float* x   = (const float*)d_in[0];
    const float* w1  = (const float*)d_in[1];
    const float* b1  = (const float*)d_in[2];
    const float* w2  = (const float*)d_in[3];
    const float* b2  = (const float*)d_in[4];
    const float* w3  = (const float*)d_in[5];
    const float* b3  = (const float*)d_in[6];
    const float* sw1 = (const float*)d_in[7];
    const float* sb1 = (const float*)d_in[8];
    const float* sw2 = (const float*)d_in[9];
    const float* sb2 = (const float*)d_in[10];
    const float* sw3 = (const float*)d_in[11];
    const float* sb3 = (const float*)d_in[12];
    const float* cw1 = (const float*)d_in[13];
    const float* cb1 = (const float*)d_in[14];
    const float* cw2 = (const float*)d_in[15];
    const float* cb2 = (const float*)d_in[16];
    float* out = (float*)d_out;

    // weight transposes
    k_transpose<<<(64*768 + 255)/256, 256>>>(w1,  0, 64, 768);
    k_transpose<<<(64*64  + 255)/256, 256>>>(w2,  1, 64, 64);
    k_transpose<<<(16*64  + 255)/256, 256>>>(w3,  2, 16, 64);
    k_transpose<<<(64*384 + 255)/256, 256>>>(sw1, 3, 64, 384);
    k_transpose<<<(64*64  + 255)/256, 256>>>(sw2, 4, 64, 64);
    k_transpose<<<(16*64  + 255)/256, 256>>>(sw3, 5, 16, 64);
    k_transpose<<<(48*144 + 255)/256, 256>>>(cw1, 6, 48, 144);
    k_transpose<<<(16*432 + 255)/256, 256>>>(cw2, 7, 16, 432);

    k_prefix<<<1, 256>>>(x);
    k_precompute<<<dim3(1026, 3), 64>>>(x, b1);
    k_zero<<<8192, 256>>>();
    k_pair<<<TILES, 256>>>(x, b2, b3);
    k_conv1<<<dim3(33, 33, 2), 256>>>(cb1);
    k_conv2<<<dim3(32, 32, 2), 256>>>(cb2, out);
    k_skip<<<1022, 64>>>(x, sb1, sb2, sb3, out);
}

// round 8
// speedup vs baseline: 1.0106x; 1.0106x over previous
#include <cuda_runtime.h>

#define NN 512
#define BB 2
#define DD 128
#define OO 16
#define HH 64
#define CHN 48
#define MROWS 262656
#define TILES 4104
#define H1DIM 514
#define SKIP_OFF (512*512*2*16)

typedef unsigned long long ull;

// ---------------- packed f32x2 helpers (Blackwell FFMA2 via PTX) ----------------
__device__ __forceinline__ ull pk2(float lo, float hi){
    ull r; asm("mov.b64 %0, {%1,%2};" : "=l"(r) : "f"(lo), "f"(hi)); return r;
}
__device__ __forceinline__ ull dup2(float v){ return pk2(v, v); }
__device__ __forceinline__ float2 upk2(ull p){
    float2 r; asm("mov.b64 {%0,%1}, %2;" : "=f"(r.x), "=f"(r.y) : "l"(p)); return r;
}
__device__ __forceinline__ void fma2(ull &d, ull a, ull b){
    asm("fma.rn.f32x2 %0, %1, %2, %0;" : "+l"(d) : "l"(a), "l"(b));
}

// ---------------- scratch (device globals; no allocation allowed) ----------------
__device__ __align__(16) float g_xc[513*256];
__device__ __align__(16) float g_x2c[513*256];
__device__ __align__(16) float g_x3c[513*256];
__device__ __align__(16) float g_w1T[768*64];
__device__ __align__(16) float g_w2T[64*64];
__device__ __align__(16) float g_w3T[64*16];
__device__ __align__(16) float g_sw1T[384*64];
__device__ __align__(16) float g_sw2T[64*64];
__device__ __align__(16) float g_sw3T[64*16];
__device__ __align__(16) float g_cw1T[16*9*48];
__device__ __align__(16) float g_cw2T[48*9*16];
__device__ __align__(16) float g_A[1024*64];    // x_i . Wseg0 + b1
__device__ __align__(16) float g_Bv[1024*64];   // x_j . Wseg1
__device__ __align__(16) float g_M[1026*64];    // moment cumsum projections
__device__ __align__(16) float g_S[BB*OO*NN*NN];           // conv1 input, NCHW
__device__ __align__(16) float g_H1[BB*CHN*H1DIM*H1DIM];   // conv1 output

__device__ __forceinline__ float gelu(float v){ return v * normcdff(v); }

// ---------------- weight transposes: [O,K] -> [K,O] ----------------
__global__ void k_transpose(const float* __restrict__ src, int which, int Osz, int Ksz){
    float* dst;
    switch(which){
        case 0: dst = g_w1T;  break;
        case 1: dst = g_w2T;  break;
        case 2: dst = g_w3T;  break;
        case 3: dst = g_sw1T; break;
        case 4: dst = g_sw2T; break;
        case 5: dst = g_sw3T; break;
        case 6: dst = g_cw1T; break;
        default: dst = g_cw2T; break;
    }
    int idx = blockIdx.x*blockDim.x + threadIdx.x;
    if (idx < Osz*Ksz){
        int o = idx / Ksz, k = idx - o*Ksz;
        dst[k*Osz + o] = src[idx];
    }
}

// ---------------- prefix sums of moments (513 rows x 256 cols) ----------------
__global__ void k_prefix(const float* __restrict__ x){
    int col = threadIdx.x; // 256 = b*128 + d
    float c1 = 0.f, c2 = 0.f, c3 = 0.f;
    g_xc[col] = 0.f; g_x2c[col] = 0.f; g_x3c[col] = 0.f;
    for (int n = 0; n < NN; n++){
        float v = x[n*256 + col];
        c1 += v; c2 += v*v; c3 += v*v*v;
        g_xc [(n+1)*256 + col] = c1;
        g_x2c[(n+1)*256 + col] = c2;
        g_x3c[(n+1)*256 + col] = c3;
    }
}

// ---------------- separable layer-1 precomputes ----------------
__global__ void k_precompute(const float* __restrict__ x, const float* __restrict__ b1){
    int type = blockIdx.y;      // 0: A, 1: Bv, 2: M
    int rid  = blockIdx.x;
    int t    = threadIdx.x;     // 64 threads, one output channel each
    __shared__ float sIn[384];
    if (type < 2){
        if (rid >= 1024) return;
        const float* xr = x + rid*128;       // rid = i*2 + b
        sIn[t] = xr[t]; sIn[64+t] = xr[64+t];
        __syncthreads();
        float acc = (type == 0) ? b1[t] : 0.f;
        const float* w = g_w1T + (type == 0 ? 0 : 128)*64 + t;
        #pragma unroll 4
        for (int d = 0; d < 128; d++) acc += sIn[d] * w[d*64];
        (type == 0 ? g_A : g_Bv)[rid*64 + t] = acc;
    } else {
        const float* c1 = g_xc  + rid*128;   // rid = r*2 + b, r in [0,512]
        const float* c2 = g_x2c + rid*128;
        const float* c3 = g_x3c + rid*128;
        sIn[t]       = c1[t]; sIn[64+t]  = c1[64+t];
        sIn[128+t]   = c2[t]; sIn[192+t] = c2[64+t];
        sIn[256+t]   = c3[t]; sIn[320+t] = c3[64+t];
        __syncthreads();
        float acc = 0.f;
        #pragma unroll 4
        for (int d = 0; d < 128; d++){
            acc += sIn[d]       * g_w1T[(384+d)*64 + t];
            acc += sIn[128 + d] * g_w1T[(512+d)*64 + t];
            acc += sIn[256 + d] * g_w1T[(640+d)*64 + t];
        }
        g_M[rid*64 + t] = acc;
    }
}

// ---------------- zero dense S (upper triangle must be 0) ----------------
__global__ void k_zero(){
    int idx = blockIdx.x*blockDim.x + threadIdx.x;
    ((float4*)g_S)[idx] = make_float4(0.f, 0.f, 0.f, 0.f);
}

// ---------------- pair MLP: 64-row tiles, full 3-layer fused, FFMA2 inner loops ----------------
__global__ void __launch_bounds__(256) k_pair(const float* __restrict__ x,
                                              const float* __restrict__ b2,
                                              const float* __restrict__ b3){
    __shared__ __align__(16) float sA[64*68];   // [k][row], pad 68
    __shared__ __align__(16) float sB[64*64];   // [k][col]
    __shared__ int   sI[64], sJ[64];
    __shared__ float sInvL[64];

    int tid  = threadIdx.x;
    int base = blockIdx.x * 64;

    if (tid < 64){
        int m = base + tid;
        int p = m >> 1;
        int i = (int)floorf((sqrtf(8.0f*(float)p + 1.0f) - 1.0f) * 0.5f);
        while ((i+1)*(i+2)/2 <= p) i++;
        while (i*(i+1)/2 > p)      i--;
        int j = p - i*(i+1)/2;
        sI[tid] = i; sJ[tid] = j;
        sInvL[tid] = 1.0f / (float)(i - j + 1);
    }
    __syncthreads();

    int tr = tid >> 4, tc = tid & 15;
    ull acc2[4][2];
    #pragma unroll
    for (int a = 0; a < 4; a++){ acc2[a][0] = 0ull; acc2[a][1] = 0ull; }

    int row = tid >> 2;
    int dg  = tid & 3;
    int i_r = sI[row], j_r = sJ[row];
    int b_r = (base + row) & 1;
    const float* xi = x + (i_r*2 + b_r)*128 + dg*16;
    const float* xj = x + (j_r*2 + b_r)*128 + dg*16;

    // ---- layer 1: only the curA*curB segment needs a pairwise GEMM (K=128) ----
    for (int kc = 0; kc < 2; kc++){
        int d0 = kc*64;
        #pragma unroll
        for (int q = 0; q < 4; q++){
            float4 a4 = *(const float4*)(xi + d0 + 4*q);
            float4 c4 = *(const float4*)(xj + d0 + 4*q);
            int kk = dg*16 + 4*q;
            sA[(kk+0)*68 + row] = a4.x*c4.x;
            sA[(kk+1)*68 + row] = a4.y*c4.y;
            sA[(kk+2)*68 + row] = a4.z*c4.z;
            sA[(kk+3)*68 + row] = a4.w*c4.w;
        }
        {
            const float4* src = (const float4*)(g_w1T + (256 + d0)*64);
            float4* dst4 = (float4*)sB;
            #pragma unroll
            for (int q = 0; q < 4; q++) dst4[q*256 + tid] = src[q*256 + tid];
        }
        __syncthreads();
        #pragma unroll 8
        for (int kk = 0; kk < 64; kk++){
            float4 a4 = *(const float4*)&sA[kk*68 + tr*4];
            ulonglong2 bb4 = *(const ulonglong2*)&sB[kk*64 + tc*4];
            ull ax = dup2(a4.x), ay = dup2(a4.y), az = dup2(a4.z), aw = dup2(a4.w);
            fma2(acc2[0][0], ax, bb4.x); fma2(acc2[0][1], ax, bb4.y);
            fma2(acc2[1][0], ay, bb4.x); fma2(acc2[1][1], ay, bb4.y);
            fma2(acc2[2][0], az, bb4.x); fma2(acc2[2][1], az, bb4.y);
            fma2(acc2[3][0], aw, bb4.x); fma2(acc2[3][1], aw, bb4.y);
        }
        __syncthreads();
    }

    // ---- add separable precomputes (A[i] + Bv[j] + invL*(M[i+1]-M[j])) via sB ----
    #pragma unroll
    for (int u = 0; u < 16; u++){
        int idx = u*256 + tid;
        int r2 = idx >> 6, oc = idx & 63;
        int ii = sI[r2], jj = sJ[r2];
        int bb = (base + r2) & 1;
        float pre = g_A[(ii*2+bb)*64 + oc] + g_Bv[(jj*2+bb)*64 + oc]
                  + sInvL[r2] * (g_M[((ii+1)*2+bb)*64 + oc] - g_M[(jj*2+bb)*64 + oc]);
        sB[r2*64 + oc] = pre;
    }
    __syncthreads();

    #pragma unroll
    for (int a = 0; a < 4; a++){
        float2 p0 = upk2(acc2[a][0]);
        float2 p1 = upk2(acc2[a][1]);
        int r = tr*4 + a;
        sA[(tc*4+0)*68 + r] = gelu(p0.x + sB[r*64 + tc*4 + 0]);
        sA[(tc*4+1)*68 + r] = gelu(p0.y + sB[r*64 + tc*4 + 1]);
        sA[(tc*4+2)*68 + r] = gelu(p1.x + sB[r*64 + tc*4 + 2]);
        sA[(tc*4+3)*68 + r] = gelu(p1.y + sB[r*64 + tc*4 + 3]);
        acc2[a][0] = 0ull; acc2[a][1] = 0ull;
    }
    __syncthreads();

    // ---- layer 2 (K=64) ----
    {
        const float4* src = (const float4*)g_w2T;
        float4* dst4 = (float4*)sB;
        #pragma unroll
        for (int q = 0; q < 4; q++) dst4[q*256 + tid] = src[q*256 + tid];
    }
    __syncthreads();
    #pragma unroll 8
    for (int kk = 0; kk < 64; kk++){
        float4 a4 = *(const float4*)&sA[kk*68 + tr*4];
        ulonglong2 bb4 = *(const ulonglong2*)&sB[kk*64 + tc*4];
        ull ax = dup2(a4.x), ay = dup2(a4.y), az = dup2(a4.z), aw = dup2(a4.w);
        fma2(acc2[0][0], ax, bb4.x); fma2(acc2[0][1], ax, bb4.y);
        fma2(acc2[1][0], ay, bb4.x); fma2(acc2[1][1], ay, bb4.y);
        fma2(acc2[2][0], az, bb4.x); fma2(acc2[2][1], az, bb4.y);
        fma2(acc2[3][0], aw, bb4.x); fma2(acc2[3][1], aw, bb4.y);
    }
    __syncthreads();

    {
        float bv0 = b2[tc*4+0], bv1 = b2[tc*4+1], bv2 = b2[tc*4+2], bv3 = b2[tc*4+3];
        #pragma unroll
        for (int a = 0; a < 4; a++){
            float2 p0 = upk2(acc2[a][0]);
            float2 p1 = upk2(acc2[a][1]);
            int r = tr*4 + a;
            sA[(tc*4+0)*68 + r] = gelu(p0.x + bv0);
            sA[(tc*4+1)*68 + r] = gelu(p0.y + bv1);
            sA[(tc*4+2)*68 + r] = gelu(p1.x + bv2);
            sA[(tc*4+3)*68 + r] = gelu(p1.y + bv3);
        }
    }
    if (tid < 256) ((float4*)sB)[tid] = ((const float4*)g_w3T)[tid];  // 1024 floats
    __syncthreads();

    // ---- layer 3 (64 -> 16) + scatter into NCHW S ----
    int r3 = tid >> 2;
    int og = (tid & 3) * 4;
    ull o01 = pk2(b3[og], b3[og+1]);
    ull o23 = pk2(b3[og+2], b3[og+3]);
    #pragma unroll 8
    for (int kk = 0; kk < 64; kk++){
        ull av = dup2(sA[kk*68 + r3]);
        ulonglong2 w2v = *(const ulonglong2*)&sB[kk*16 + og];
        fma2(o01, av, w2v.x);
        fma2(o23, av, w2v.y);
    }
    float2 r01 = upk2(o01), r23 = upk2(o23);
    int ii = sI[r3], jj = sJ[r3], bb = (base + r3) & 1;
    float* dst = g_S + (((bb*16 + og)*512 + ii)*512 + jj);
    dst[0]           = r01.x;
    dst[512*512]     = r01.y;
    dst[2*512*512]   = r23.x;
    dst[3*512*512]   = r23.y;
}

// ---------------- conv1: 16->48, 3x3, pad=2, out 514x514, fused GELU, FFMA2 ----------------
__global__ void __launch_bounds__(256) k_conv1(const float* __restrict__ cb1){
    __shared__ float sIn[16*18*18];                  // 20736 B
    __shared__ __align__(16) float sW[16*9*48];      // 27648 B
    int b  = blockIdx.z;
    int by = blockIdx.y, bx = blockIdx.x;
    int tid = threadIdx.x;

    for (int idx = tid; idx < 16*9*48/4; idx += 256)
        ((float4*)sW)[idx] = ((const float4*)g_cw1T)[idx];

    int y0 = by*16 - 2, x0 = bx*16 - 2;
    for (int idx = tid; idx < 5184; idx += 256){
        int ic = idx / 324; int rem = idx - ic*324;
        int ly = rem / 18,  lx = rem - ly*18;
        int gy = y0 + ly,   gx = x0 + lx;
        float v = 0.f;
        if ((unsigned)gy < 512u && (unsigned)gx < 512u)
            v = g_S[((b*16 + ic)*512 + gy)*512 + gx];
        sIn[idx] = v;
    }
    __syncthreads();

    int ty = tid >> 4, tx = tid & 15;
    ull acc2[12][2];
    #pragma unroll
    for (int q = 0; q < 12; q++){ acc2[q][0] = 0ull; acc2[q][1] = 0ull; }

    #pragma unroll 1
    for (int ic = 0; ic < 16; ic++){
        float v[9];
        #pragma unroll
        for (int ky = 0; ky < 3; ky++)
            #pragma unroll
            for (int kx = 0; kx < 3; kx++)
                v[ky*3+kx] = sIn[ic*324 + (ty+ky)*18 + (tx+kx)];
        #pragma unroll
        for (int tap = 0; tap < 9; tap++){
            ull vv2 = dup2(v[tap]);
            const ulonglong2* wp = (const ulonglong2*)&sW[(ic*9 + tap)*48];
            #pragma unroll
            for (int q = 0; q < 12; q++){
                ulonglong2 w4 = wp[q];
                fma2(acc2[q][0], vv2, w4.x);
                fma2(acc2[q][1], vv2, w4.y);
            }
        }
    }

    int oy = by*16 + ty, ox = bx*16 + tx;
    if (oy < 514 && ox < 514){
        #pragma unroll
        for (int q = 0; q < 12; q++){
            float4 c = *(const float4*)&cb1[q*4];
            float2 p0 = upk2(acc2[q][0]);
            float2 p1 = upk2(acc2[q][1]);
            float* dst = g_H1 + (((b*48 + q*4)*514 + oy)*514 + ox);
            dst[0]          = gelu(p0.x + c.x);
            dst[514*514]    = gelu(p0.y + c.y);
            dst[2*514*514]  = gelu(p1.x + c.z);
            dst[3*514*514]  = gelu(p1.y + c.w);
        }
    }
}

// ---------------- conv2: 48->16, 3x3, valid, + bias + lenBA scale + permute-out, FFMA2 ----------------
__global__ void __launch_bounds__(256) k_conv2(const float* __restrict__ cb2,
                                               float* __restrict__ out){
    __shared__ float sIn[16*18*18];
    __shared__ __align__(16) float sW[16*9*16];
    int b  = blockIdx.z;
    int by = blockIdx.y, bx = blockIdx.x;
    int tid = threadIdx.x;
    int ty = tid >> 4, tx = tid & 15;

    ull acc2[4][2];
    #pragma unroll
    for (int q = 0; q < 4; q++){ acc2[q][0] = 0ull; acc2[q][1] = 0ull; }

    for (int icc = 0; icc < 3; icc++){
        if (icc) __syncthreads();
        for (int idx = tid; idx < 2304/4; idx += 256)
            ((float4*)sW)[idx] = ((const float4*)(g_cw2T + icc*2304))[idx];
        int y0 = by*16, x0 = bx*16;
        for (int idx = tid; idx < 5184; idx += 256){
            int ic = idx / 324; int rem = idx - ic*324;
            int ly = rem / 18,  lx = rem - ly*18;
            sIn[idx] = g_H1[((b*48 + icc*16 + ic)*514 + (y0+ly))*514 + (x0+lx)];
        }
        __syncthreads();
        #pragma unroll 1
        for (int ic = 0; ic < 16; ic++){
            float v[9];
            #pragma unroll
            for (int ky = 0; ky < 3; ky++)
                #pragma unroll
                for (int kx = 0; kx < 3; kx++)
                    v[ky*3+kx] = sIn[ic*324 + (ty+ky)*18 + (tx+kx)];
            #pragma unroll
            for (int tap = 0; tap < 9; tap++){
                ull vv2 = dup2(v[tap]);
                const ulonglong2* wp = (const ulonglong2*)&sW[(ic*9 + tap)*16];
                #pragma unroll
                for (int q = 0; q < 4; q++){
                    ulonglong2 w4 = wp[q];
                    fma2(acc2[q][0], vv2, w4.x);
                    fma2(acc2[q][1], vv2, w4.y);
                }
            }
        }
    }

    int oy = by*16 + ty, ox = bx*16 + tx;
    int ad = oy - ox; if (ad < 0) ad = -ad; if (ad < 1) ad = 1;
    float scale = (float)ad;
    float* dst = out + ((oy*512 + ox)*2 + b)*16;
    #pragma unroll
    for (int q = 0; q < 4; q++){
        float4 c = ((const float4*)cb2)[q];
        float2 p0 = upk2(acc2[q][0]);
        float2 p1 = upk2(acc2[q][1]);
        float4 o4;
        o4.x = scale*(p0.x + c.x);
        o4.y = scale*(p0.y + c.y);
        o4.z = scale*(p1.x + c.z);
        o4.w = scale*(p1.y + c.w);
        *(float4*)(dst + q*4) = o4;
    }
}

// ---------------- skip MLP on adjacent frames ----------------
__global__ void k_skip(const float* __restrict__ x,  const float* __restrict__ sb1,
                       const float* __restrict__ sb2, const float* __restrict__ sb3,
                       float* __restrict__ out){
    __shared__ float sIn[384], sH[64], sH2[64];
    int bid = blockIdx.x;          // 0..1021
    int tt = bid >> 1, b = bid & 1;
    int t = threadIdx.x;           // 64
    const float* xa = x + (tt*2 + b)*128;
    const float* xb = x + ((tt+1)*2 + b)*128;
    sIn[t]       = xa[t];          sIn[64+t]  = xa[64+t];
    sIn[128+t]   = xb[t];          sIn[192+t] = xb[64+t];
    sIn[256+t]   = xa[t]*xb[t];    sIn[320+t] = xa[64+t]*xb[64+t];
    __syncthreads();
    float acc = sb1[t];
    #pragma unroll 4
    for (int k = 0; k < 384; k++) acc += sIn[k] * g_sw1T[k*64 + t];
    sH[t] = gelu(acc);
    __syncthreads();
    acc = sb2[t];
    #pragma unroll 4
    for (int k = 0; k < 64; k++) acc += sH[k] * g_sw2T[k*64 + t];
    sH2[t] = gelu(acc);
    __syncthreads();
    if (t < 16){
        float a = sb3[t];
        #pragma unroll 4
        for (int k = 0; k < 64; k++) a += sH2[k] * g_sw3T[k*16 + t];
        out[SKIP_OFF + (tt*2 + b)*16 + t] = a;
    }
}

// ---------------- launch ----------------
extern "C" void kernel_launch(void* const* d_in, const int* in_sizes, int n_in,
                              void* d_out, int out_size){
    const float* x   = (const float*)d_in[0];
    const float* w1  = (const float*)d_in[1];
    const float* b1  = (const float*)d_in[2];
    const float* w2  = (const float*)d_in[3];
    const float* b2  = (const float*)d_in[4];
    const float* w3  = (const float*)d_in[5];
    const float* b3  = (const float*)d_in[6];
    const float* sw1 = (const float*)d_in[7];
    const float* sb1 = (const float*)d_in[8];
    const float* sw2 = (const float*)d_in[9];
    const float* sb2 = (const float*)d_in[10];
    const float* sw3 = (const float*)d_in[11];
    const float* sb3 = (const float*)d_in[12];
    const float* cw1 = (const float*)d_in[13];
    const float* cb1 = (const float*)d_in[14];
    const float* cw2 = (const float*)d_in[15];
    const float* cb2 = (const float*)d_in[16];
    float* out = (float*)d_out;

    // weight transposes
    k_transpose<<<(64*768 + 255)/256, 256>>>(w1,  0, 64, 768);
    k_transpose<<<(64*64  + 255)/256, 256>>>(w2,  1, 64, 64);
    k_transpose<<<(16*64  + 255)/256, 256>>>(w3,  2, 16, 64);
    k_transpose<<<(64*384 + 255)/256, 256>>>(sw1, 3, 64, 384);
    k_transpose<<<(64*64  + 255)/256, 256>>>(sw2, 4, 64, 64);
    k_transpose<<<(16*64  + 255)/256, 256>>>(sw3, 5, 16, 64);
    k_transpose<<<(48*144 + 255)/256, 256>>>(cw1, 6, 48, 144);
    k_transpose<<<(16*432 + 255)/256, 256>>>(cw2, 7, 16, 432);

    k_prefix<<<1, 256>>>(x);
    k_precompute<<<dim3(1026, 3), 64>>>(x, b1);
    k_zero<<<8192, 256>>>();
    k_pair<<<TILES, 256>>>(x, b2, b3);
    k_conv1<<<dim3(33, 33, 2), 256>>>(cb1);
    k_conv2<<<dim3(32, 32, 2), 256>>>(cb2, out);
    k_skip<<<1022, 64>>>(x, sb1, sb2, sb3, out);
}

// round 9
// speedup vs baseline: 1.0288x; 1.0180x over previous
#include <cuda_runtime.h>

#define NN 512
#define BB 2
#define DD 128
#define OO 16
#define HH 64
#define CHN 48
#define MROWS 262656
#define TILES 4104
#define H1DIM 514
#define SKIP_OFF (512*512*2*16)

typedef unsigned long long ull;

// ---------------- packed f32x2 helpers (Blackwell FFMA2 via PTX) ----------------
__device__ __forceinline__ ull pk2(float lo, float hi){
    ull r; asm("mov.b64 %0, {%1,%2};" : "=l"(r) : "f"(lo), "f"(hi)); return r;
}
__device__ __forceinline__ ull dup2(float v){ return pk2(v, v); }
__device__ __forceinline__ float2 upk2(ull p){
    float2 r; asm("mov.b64 {%0,%1}, %2;" : "=f"(r.x), "=f"(r.y) : "l"(p)); return r;
}
__device__ __forceinline__ void fma2(ull &d, ull a, ull b){
    asm("fma.rn.f32x2 %0, %1, %2, %0;" : "+l"(d) : "l"(a), "l"(b));
}

// ---------------- scratch (device globals; no allocation allowed) ----------------
__device__ __align__(16) float g_xc[513*256];
__device__ __align__(16) float g_x2c[513*256];
__device__ __align__(16) float g_x3c[513*256];
__device__ __align__(16) float g_w1T[768*64];
__device__ __align__(16) float g_w2T[64*64];
__device__ __align__(16) float g_w3T[64*16];
__device__ __align__(16) float g_sw1T[384*64];
__device__ __align__(16) float g_sw2T[64*64];
__device__ __align__(16) float g_sw3T[64*16];
__device__ __align__(16) float g_cw1T[16*9*48];
__device__ __align__(16) float g_cw2T[48*9*16];
__device__ __align__(16) float g_A[1024*64];    // x_i . Wseg0 + b1
__device__ __align__(16) float g_Bv[1024*64];   // x_j . Wseg1
__device__ __align__(16) float g_M[1026*64];    // moment cumsum projections
__device__ __align__(16) float g_S[BB*OO*NN*NN];           // conv1 input, NCHW
__device__ __align__(16) float g_H1[BB*CHN*H1DIM*H1DIM];   // conv1 output

// exact-erf GELU via erff (cheap poly path) instead of normcdff (erfcf machinery)
__device__ __forceinline__ float gelu(float v){
    return 0.5f*v*(1.0f + erff(0.70710678118654752440f*v));
}

// ---------------- all weight transposes in ONE kernel: [O,K] -> [K,O] ----------------
__global__ void k_transposeAll(const float* __restrict__ w1,  const float* __restrict__ w2,
                               const float* __restrict__ w3,  const float* __restrict__ sw1,
                               const float* __restrict__ sw2, const float* __restrict__ sw3,
                               const float* __restrict__ cw1, const float* __restrict__ cw2){
    const float* src; float* dst; int Osz, Ksz;
    switch(blockIdx.y){
        case 0: src = w1;  dst = g_w1T;  Osz = 64; Ksz = 768; break;
        case 1: src = w2;  dst = g_w2T;  Osz = 64; Ksz = 64;  break;
        case 2: src = w3;  dst = g_w3T;  Osz = 16; Ksz = 64;  break;
        case 3: src = sw1; dst = g_sw1T; Osz = 64; Ksz = 384; break;
        case 4: src = sw2; dst = g_sw2T; Osz = 64; Ksz = 64;  break;
        case 5: src = sw3; dst = g_sw3T; Osz = 16; Ksz = 64;  break;
        case 6: src = cw1; dst = g_cw1T; Osz = 48; Ksz = 144; break;
        default:src = cw2; dst = g_cw2T; Osz = 16; Ksz = 432; break;
    }
    int idx = blockIdx.x*blockDim.x + threadIdx.x;
    if (idx < Osz*Ksz){
        int o = idx / Ksz, k = idx - o*Ksz;
        dst[k*Osz + o] = src[idx];
    }
}

// ---------------- prefix sums of moments (513 rows x 256 cols) ----------------
__global__ void k_prefix(const float* __restrict__ x){
    int col = threadIdx.x; // 256 = b*128 + d
    float c1 = 0.f, c2 = 0.f, c3 = 0.f;
    g_xc[col] = 0.f; g_x2c[col] = 0.f; g_x3c[col] = 0.f;
    for (int n = 0; n < NN; n++){
        float v = x[n*256 + col];
        c1 += v; c2 += v*v; c3 += v*v*v;
        g_xc [(n+1)*256 + col] = c1;
        g_x2c[(n+1)*256 + col] = c2;
        g_x3c[(n+1)*256 + col] = c3;
    }
}

// ---------------- separable layer-1 precomputes ----------------
__global__ void k_precompute(const float* __restrict__ x, const float* __restrict__ b1){
    int type = blockIdx.y;      // 0: A, 1: Bv, 2: M
    int rid  = blockIdx.x;
    int t    = threadIdx.x;     // 64 threads, one output channel each
    __shared__ float sIn[384];
    if (type < 2){
        if (rid >= 1024) return;
        const float* xr = x + rid*128;       // rid = i*2 + b
        sIn[t] = xr[t]; sIn[64+t] = xr[64+t];
        __syncthreads();
        float acc = (type == 0) ? b1[t] : 0.f;
        const float* w = g_w1T + (type == 0 ? 0 : 128)*64 + t;
        #pragma unroll 4
        for (int d = 0; d < 128; d++) acc += sIn[d] * w[d*64];
        (type == 0 ? g_A : g_Bv)[rid*64 + t] = acc;
    } else {
        const float* c1 = g_xc  + rid*128;   // rid = r*2 + b, r in [0,512]
        const float* c2 = g_x2c + rid*128;
        const float* c3 = g_x3c + rid*128;
        sIn[t]       = c1[t]; sIn[64+t]  = c1[64+t];
        sIn[128+t]   = c2[t]; sIn[192+t] = c2[64+t];
        sIn[256+t]   = c3[t]; sIn[320+t] = c3[64+t];
        __syncthreads();
        float acc = 0.f;
        #pragma unroll 4
        for (int d = 0; d < 128; d++){
            acc += sIn[d]       * g_w1T[(384+d)*64 + t];
            acc += sIn[128 + d] * g_w1T[(512+d)*64 + t];
            acc += sIn[256 + d] * g_w1T[(640+d)*64 + t];
        }
        g_M[rid*64 + t] = acc;
    }
}

// ---------------- zero dense S (upper triangle must be 0) ----------------
__global__ void k_zero(){
    int idx = blockIdx.x*blockDim.x + threadIdx.x;
    ((float4*)g_S)[idx] = make_float4(0.f, 0.f, 0.f, 0.f);
}

// ---------------- pair MLP: 64-row tiles, full 3-layer fused, FFMA2 inner loops ----------------
__global__ void __launch_bounds__(256) k_pair(const float* __restrict__ x,
                                              const float* __restrict__ b2,
                                              const float* __restrict__ b3){
    __shared__ __align__(16) float sA[64*68];   // [k][row], pad 68
    __shared__ __align__(16) float sB[64*64];   // [k][col]
    __shared__ int   sI[64], sJ[64];
    __shared__ float sInvL[64];

    int tid  = threadIdx.x;
    int base = blockIdx.x * 64;

    if (tid < 64){
        int m = base + tid;
        int p = m >> 1;
        int i = (int)floorf((sqrtf(8.0f*(float)p + 1.0f) - 1.0f) * 0.5f);
        while ((i+1)*(i+2)/2 <= p) i++;
        while (i*(i+1)/2 > p)      i--;
        int j = p - i*(i+1)/2;
        sI[tid] = i; sJ[tid] = j;
        sInvL[tid] = 1.0f / (float)(i - j + 1);
    }
    __syncthreads();

    int tr = tid >> 4, tc = tid & 15;
    ull acc2[4][2];
    #pragma unroll
    for (int a = 0; a < 4; a++){ acc2[a][0] = 0ull; acc2[a][1] = 0ull; }

    int row = tid >> 2;
    int dg  = tid & 3;
    int i_r = sI[row], j_r = sJ[row];
    int b_r = (base + row) & 1;
    const float* xi = x + (i_r*2 + b_r)*128 + dg*16;
    const float* xj = x + (j_r*2 + b_r)*128 + dg*16;

    // ---- layer 1: only the curA*curB segment needs a pairwise GEMM (K=128) ----
    for (int kc = 0; kc < 2; kc++){
        int d0 = kc*64;
        #pragma unroll
        for (int q = 0; q < 4; q++){
            float4 a4 = *(const float4*)(xi + d0 + 4*q);
            float4 c4 = *(const float4*)(xj + d0 + 4*q);
            int kk = dg*16 + 4*q;
            sA[(kk+0)*68 + row] = a4.x*c4.x;
            sA[(kk+1)*68 + row] = a4.y*c4.y;
            sA[(kk+2)*68 + row] = a4.z*c4.z;
            sA[(kk+3)*68 + row] = a4.w*c4.w;
        }
        {
            const float4* src = (const float4*)(g_w1T + (256 + d0)*64);
            float4* dst4 = (float4*)sB;
            #pragma unroll
            for (int q = 0; q < 4; q++) dst4[q*256 + tid] = src[q*256 + tid];
        }
        __syncthreads();
        #pragma unroll 8
        for (int kk = 0; kk < 64; kk++){
            float4 a4 = *(const float4*)&sA[kk*68 + tr*4];
            ulonglong2 bb4 = *(const ulonglong2*)&sB[kk*64 + tc*4];
            ull ax = dup2(a4.x), ay = dup2(a4.y), az = dup2(a4.z), aw = dup2(a4.w);
            fma2(acc2[0][0], ax, bb4.x); fma2(acc2[0][1], ax, bb4.y);
            fma2(acc2[1][0], ay, bb4.x); fma2(acc2[1][1], ay, bb4.y);
            fma2(acc2[2][0], az, bb4.x); fma2(acc2[2][1], az, bb4.y);
            fma2(acc2[3][0], aw, bb4.x); fma2(acc2[3][1], aw, bb4.y);
        }
        __syncthreads();
    }

    // ---- add separable precomputes (A[i] + Bv[j] + invL*(M[i+1]-M[j])) via sB ----
    #pragma unroll
    for (int u = 0; u < 16; u++){
        int idx = u*256 + tid;
        int r2 = idx >> 6, oc = idx & 63;
        int ii = sI[r2], jj = sJ[r2];
        int bb = (base + r2) & 1;
        float pre = g_A[(ii*2+bb)*64 + oc] + g_Bv[(jj*2+bb)*64 + oc]
                  + sInvL[r2] * (g_M[((ii+1)*2+bb)*64 + oc] - g_M[(jj*2+bb)*64 + oc]);
        sB[r2*64 + oc] = pre;
    }
    __syncthreads();

    #pragma unroll
    for (int a = 0; a < 4; a++){
        float2 p0 = upk2(acc2[a][0]);
        float2 p1 = upk2(acc2[a][1]);
        int r = tr*4 + a;
        sA[(tc*4+0)*68 + r] = gelu(p0.x + sB[r*64 + tc*4 + 0]);
        sA[(tc*4+1)*68 + r] = gelu(p0.y + sB[r*64 + tc*4 + 1]);
        sA[(tc*4+2)*68 + r] = gelu(p1.x + sB[r*64 + tc*4 + 2]);
        sA[(tc*4+3)*68 + r] = gelu(p1.y + sB[r*64 + tc*4 + 3]);
        acc2[a][0] = 0ull; acc2[a][1] = 0ull;
    }
    __syncthreads();

    // ---- layer 2 (K=64) ----
    {
        const float4* src = (const float4*)g_w2T;
        float4* dst4 = (float4*)sB;
        #pragma unroll
        for (int q = 0; q < 4; q++) dst4[q*256 + tid] = src[q*256 + tid];
    }
    __syncthreads();
    #pragma unroll 8
    for (int kk = 0; kk < 64; kk++){
        float4 a4 = *(const float4*)&sA[kk*68 + tr*4];
        ulonglong2 bb4 = *(const ulonglong2*)&sB[kk*64 + tc*4];
        ull ax = dup2(a4.x), ay = dup2(a4.y), az = dup2(a4.z), aw = dup2(a4.w);
        fma2(acc2[0][0], ax, bb4.x); fma2(acc2[0][1], ax, bb4.y);
        fma2(acc2[1][0], ay, bb4.x); fma2(acc2[1][1], ay, bb4.y);
        fma2(acc2[2][0], az, bb4.x); fma2(acc2[2][1], az, bb4.y);
        fma2(acc2[3][0], aw, bb4.x); fma2(acc2[3][1], aw, bb4.y);
    }
    __syncthreads();

    {
        float bv0 = b2[tc*4+0], bv1 = b2[tc*4+1], bv2 = b2[tc*4+2], bv3 = b2[tc*4+3];
        #pragma unroll
        for (int a = 0; a < 4; a++){
            float2 p0 = upk2(acc2[a][0]);
            float2 p1 = upk2(acc2[a][1]);
            int r = tr*4 + a;
            sA[(tc*4+0)*68 + r] = gelu(p0.x + bv0);
            sA[(tc*4+1)*68 + r] = gelu(p0.y + bv1);
            sA[(tc*4+2)*68 + r] = gelu(p1.x + bv2);
            sA[(tc*4+3)*68 + r] = gelu(p1.y + bv3);
        }
    }
    if (tid < 256) ((float4*)sB)[tid] = ((const float4*)g_w3T)[tid];  // 1024 floats
    __syncthreads();

    // ---- layer 3 (64 -> 16) + scatter into NCHW S ----
    int r3 = tid >> 2;
    int og = (tid & 3) * 4;
    ull o01 = pk2(b3[og], b3[og+1]);
    ull o23 = pk2(b3[og+2], b3[og+3]);
    #pragma unroll 8
    for (int kk = 0; kk < 64; kk++){
        ull av = dup2(sA[kk*68 + r3]);
        ulonglong2 w2v = *(const ulonglong2*)&sB[kk*16 + og];
        fma2(o01, av, w2v.x);
        fma2(o23, av, w2v.y);
    }
    float2 r01 = upk2(o01), r23 = upk2(o23);
    int ii = sI[r3], jj = sJ[r3], bb = (base + r3) & 1;
    float* dst = g_S + (((bb*16 + og)*512 + ii)*512 + jj);
    dst[0]           = r01.x;
    dst[512*512]     = r01.y;
    dst[2*512*512]   = r23.x;
    dst[3*512*512]   = r23.y;
}

// ---------------- conv1: 16->48, 3x3, pad=2, out 514x514, fused GELU, FFMA2 ----------------
__global__ void __launch_bounds__(256) k_conv1(const float* __restrict__ cb1){
    __shared__ float sIn[16*18*18];                  // 20736 B
    __shared__ __align__(16) float sW[16*9*48];      // 27648 B
    int b  = blockIdx.z;
    int by = blockIdx.y, bx = blockIdx.x;
    int tid = threadIdx.x;

    for (int idx = tid; idx < 16*9*48/4; idx += 256)
        ((float4*)sW)[idx] = ((const float4*)g_cw1T)[idx];

    int y0 = by*16 - 2, x0 = bx*16 - 2;
    for (int idx = tid; idx < 5184; idx += 256){
        int ic = idx / 324; int rem = idx - ic*324;
        int ly = rem / 18,  lx = rem - ly*18;
        int gy = y0 + ly,   gx = x0 + lx;
        float v = 0.f;
        if ((unsigned)gy < 512u && (unsigned)gx < 512u)
            v = g_S[((b*16 + ic)*512 + gy)*512 + gx];
        sIn[idx] = v;
    }
    __syncthreads();

    int ty = tid >> 4, tx = tid & 15;
    ull acc2[12][2];
    #pragma unroll
    for (int q = 0; q < 12; q++){ acc2[q][0] = 0ull; acc2[q][1] = 0ull; }

    #pragma unroll 1
    for (int ic = 0; ic < 16; ic++){
        float v[9];
        #pragma unroll
        for (int ky = 0; ky < 3; ky++)
            #pragma unroll
            for (int kx = 0; kx < 3; kx++)
                v[ky*3+kx] = sIn[ic*324 + (ty+ky)*18 + (tx+kx)];
        #pragma unroll
        for (int tap = 0; tap < 9; tap++){
            ull vv2 = dup2(v[tap]);
            const ulonglong2* wp = (const ulonglong2*)&sW[(ic*9 + tap)*48];
            #pragma unroll
            for (int q = 0; q < 12; q++){
                ulonglong2 w4 = wp[q];
                fma2(acc2[q][0], vv2, w4.x);
                fma2(acc2[q][1], vv2, w4.y);
            }
        }
    }

    int oy = by*16 + ty, ox = bx*16 + tx;
    if (oy < 514 && ox < 514){
        #pragma unroll
        for (int q = 0; q < 12; q++){
            float4 c = *(const float4*)&cb1[q*4];
            float2 p0 = upk2(acc2[q][0]);
            float2 p1 = upk2(acc2[q][1]);
            float* dst = g_H1 + (((b*48 + q*4)*514 + oy)*514 + ox);
            dst[0]          = gelu(p0.x + c.x);
            dst[514*514]    = gelu(p0.y + c.y);
            dst[2*514*514]  = gelu(p1.x + c.z);
            dst[3*514*514]  = gelu(p1.y + c.w);
        }
    }
}

// ---------------- conv2: 48->16, 3x3, valid, + bias + lenBA scale + permute-out, FFMA2 ----------------
__global__ void __launch_bounds__(256) k_conv2(const float* __restrict__ cb2,
                                               float* __restrict__ out){
    __shared__ float sIn[16*18*18];
    __shared__ __align__(16) float sW[16*9*16];
    int b  = blockIdx.z;
    int by = blockIdx.y, bx = blockIdx.x;
    int tid = threadIdx.x;
    int ty = tid >> 4, tx = tid & 15;

    ull acc2[4][2];
    #pragma unroll
    for (int q = 0; q < 4; q++){ acc2[q][0] = 0ull; acc2[q][1] = 0ull; }

    for (int icc = 0; icc < 3; icc++){
        if (icc) __syncthreads();
        for (int idx = tid; idx < 2304/4; idx += 256)
            ((float4*)sW)[idx] = ((const float4*)(g_cw2T + icc*2304))[idx];
        int y0 = by*16, x0 = bx*16;
        for (int idx = tid; idx < 5184; idx += 256){
            int ic = idx / 324; int rem = idx - ic*324;
            int ly = rem / 18,  lx = rem - ly*18;
            sIn[idx] = g_H1[((b*48 + icc*16 + ic)*514 + (y0+ly))*514 + (x0+lx)];
        }
        __syncthreads();
        #pragma unroll 1
        for (int ic = 0; ic < 16; ic++){
            float v[9];
            #pragma unroll
            for (int ky = 0; ky < 3; ky++)
                #pragma unroll
                for (int kx = 0; kx < 3; kx++)
                    v[ky*3+kx] = sIn[ic*324 + (ty+ky)*18 + (tx+kx)];
            #pragma unroll
            for (int tap = 0; tap < 9; tap++){
                ull vv2 = dup2(v[tap]);
                const ulonglong2* wp = (const ulonglong2*)&sW[(ic*9 + tap)*16];
                #pragma unroll
                for (int q = 0; q < 4; q++){
                    ulonglong2 w4 = wp[q];
                    fma2(acc2[q][0], vv2, w4.x);
                    fma2(acc2[q][1], vv2, w4.y);
                }
            }
        }
    }

    int oy = by*16 + ty, ox = bx*16 + tx;
    int ad = oy - ox; if (ad < 0) ad = -ad; if (ad < 1) ad = 1;
    float scale = (float)ad;
    float* dst = out + ((oy*512 + ox)*2 + b)*16;
    #pragma unroll
    for (int q = 0; q < 4; q++){
        float4 c = ((const float4*)cb2)[q];
        float2 p0 = upk2(acc2[q][0]);
        float2 p1 = upk2(acc2[q][1]);
        float4 o4;
        o4.x = scale*(p0.x + c.x);
        o4.y = scale*(p0.y + c.y);
        o4.z = scale*(p1.x + c.z);
        o4.w = scale*(p1.y + c.w);
        *(float4*)(dst + q*4) = o4;
    }
}

// ---------------- skip MLP on adjacent frames ----------------
__global__ void k_skip(const float* __restrict__ x,  const float* __restrict__ sb1,
                       const float* __restrict__ sb2, const float* __restrict__ sb3,
                       float* __restrict__ out){
    __shared__ float sIn[384], sH[64], sH2[64];
    int bid = blockIdx.x;          // 0..1021
    int tt = bid >> 1, b = bid & 1;
    int t = threadIdx.x;           // 64
    const float* xa = x + (tt*2 + b)*128;
    const float* xb = x + ((tt+1)*2 + b)*128;
    sIn[t]       = xa[t];          sIn[64+t]  = xa[64+t];
    sIn[128+t]   = xb[t];          sIn[192+t] = xb[64+t];
    sIn[256+t]   = xa[t]*xb[t];    sIn[320+t] = xa[64+t]*xb[64+t];
    __syncthreads();
    float acc = sb1[t];
    #pragma unroll 4
    for (int k = 0; k < 384; k++) acc += sIn[k] * g_sw1T[k*64 + t];
    sH[t] = gelu(acc);
    __syncthreads();
    acc = sb2[t];
    #pragma unroll 4
    for (int k = 0; k < 64; k++) acc += sH[k] * g_sw2T[k*64 + t];
    sH2[t] = gelu(acc);
    __syncthreads();
    if (t < 16){
        float a = sb3[t];
        #pragma unroll 4
        for (int k = 0; k < 64; k++) a += sH2[k] * g_sw3T[k*16 + t];
        out[SKIP_OFF + (tt*2 + b)*16 + t] = a;
    }
}

// ---------------- launch ----------------
// Launch order is deliberate: ncu capture uses -s 5 -c 1, so the 6th launch
// below (k_pair) is the one that gets profiled.
extern "C" void kernel_launch(void* const* d_in, const int* in_sizes, int n_in,
                              void* d_out, int out_size){
    const float* x   = (const float*)d_in[0];
    const float* w1  = (const float*)d_in[1];
    const float* b1  = (const float*)d_in[2];
    const float* w2  = (const float*)d_in[3];
    const float* b2  = (const float*)d_in[4];
    const float* w3  = (const float*)d_in[5];
    const float* b3  = (const float*)d_in[6];
    const float* sw1 = (const float*)d_in[7];
    const float* sb1 = (const float*)d_in[8];
    const float* sw2 = (const float*)d_in[9];
    const float* sb2 = (const float*)d_in[10];
    const float* sw3 = (const float*)d_in[11];
    const float* sb3 = (const float*)d_in[12];
    const float* cw1 = (const float*)d_in[13];
    const float* cb1 = (const float*)d_in[14];
    const float* cw2 = (const float*)d_in[15];
    const float* cb2 = (const float*)d_in[16];
    float* out = (float*)d_out;

    k_transposeAll<<<dim3(192, 8), 256>>>(w1, w2, w3, sw1, sw2, sw3, cw1, cw2); // 1
    k_prefix<<<1, 256>>>(x);                                                    // 2
    k_precompute<<<dim3(1026, 3), 64>>>(x, b1);                                 // 3
    k_zero<<<8192, 256>>>();                                                    // 4
    k_skip<<<1022, 64>>>(x, sb1, sb2, sb3, out);                                // 5
    k_pair<<<TILES, 256>>>(x, b2, b3);                                          // 6 <- profiled
    k_conv1<<<dim3(33, 33, 2), 256>>>(cb1);                                     // 7
    k_conv2<<<dim3(32, 32, 2), 256>>>(cb2, out);                                // 8
}

// round 10
// speedup vs baseline: 1.2872x; 1.2512x over previous
#include <cuda_runtime.h>

#define NN 512
#define BB 2
#define DD 128
#define OO 16
#define HH 64
#define CHN 48
#define TILES 4104
#define H1DIM 514
#define SKIP_OFF (512*512*2*16)

typedef unsigned long long ull;

// ---------------- packed f32x2 helpers (Blackwell FFMA2 via PTX) ----------------
__device__ __forceinline__ ull pk2(float lo, float hi){
    ull r; asm("mov.b64 %0, {%1,%2};" : "=l"(r) : "f"(lo), "f"(hi)); return r;
}
__device__ __forceinline__ ull dup2(float v){ return pk2(v, v); }
__device__ __forceinline__ float2 upk2(ull p){
    float2 r; asm("mov.b64 {%0,%1}, %2;" : "=f"(r.x), "=f"(r.y) : "l"(p)); return r;
}
__device__ __forceinline__ void fma2(ull &d, ull a, ull b){
    asm("fma.rn.f32x2 %0, %1, %2, %0;" : "+l"(d) : "l"(a), "l"(b));
}

// ---------------- scratch (device globals; no allocation allowed) ----------------
__device__ __align__(16) float g_xc[513*256];
__device__ __align__(16) float g_x2c[513*256];
__device__ __align__(16) float g_x3c[513*256];
__device__ __align__(16) float g_w1T[768*64];
__device__ __align__(16) float g_w2T[64*64];
__device__ __align__(16) float g_w3T[64*16];
__device__ __align__(16) float g_sw1T[384*64];
__device__ __align__(16) float g_sw2T[64*64];
__device__ __align__(16) float g_sw3T[64*16];
__device__ __align__(16) float g_cw1T[16*9*48];
__device__ __align__(16) float g_cw2T[48*9*16];
__device__ __align__(16) float g_A[1024*64];    // x_i . Wseg0 + b1
__device__ __align__(16) float g_Bv[1024*64];   // x_j . Wseg1
__device__ __align__(16) float g_M[1026*64];    // moment cumsum projections
__device__ __align__(16) float g_Kc[16];        // conv2 constant for far-upper region
__device__ __align__(16) float g_S[BB*OO*NN*NN];           // conv1 input, NCHW
__device__ __align__(16) float g_H1[BB*CHN*H1DIM*H1DIM];   // conv1 output

// exact-erf GELU via erff
__device__ __forceinline__ float gelu(float v){
    return 0.5f*v*(1.0f + erff(0.70710678118654752440f*v));
}

// ---------------- all weight transposes in ONE kernel: [O,K] -> [K,O] ----------------
__global__ void k_transposeAll(const float* __restrict__ w1,  const float* __restrict__ w2,
                               const float* __restrict__ w3,  const float* __restrict__ sw1,
                               const float* __restrict__ sw2, const float* __restrict__ sw3,
                               const float* __restrict__ cw1, const float* __restrict__ cw2){
    const float* src; float* dst; int Osz, Ksz;
    switch(blockIdx.y){
        case 0: src = w1;  dst = g_w1T;  Osz = 64; Ksz = 768; break;
        case 1: src = w2;  dst = g_w2T;  Osz = 64; Ksz = 64;  break;
        case 2: src = w3;  dst = g_w3T;  Osz = 16; Ksz = 64;  break;
        case 3: src = sw1; dst = g_sw1T; Osz = 64; Ksz = 384; break;
        case 4: src = sw2; dst = g_sw2T; Osz = 64; Ksz = 64;  break;
        case 5: src = sw3; dst = g_sw3T; Osz = 16; Ksz = 64;  break;
        case 6: src = cw1; dst = g_cw1T; Osz = 48; Ksz = 144; break;
        default:src = cw2; dst = g_cw2T; Osz = 16; Ksz = 432; break;
    }
    int idx = blockIdx.x*blockDim.x + threadIdx.x;
    if (idx < Osz*Ksz){
        int o = idx / Ksz, k = idx - o*Ksz;
        dst[k*Osz + o] = src[idx];
    }
}

// ---------------- prefix sums of moments (513 rows x 256 cols), 8-deep load batching ----------------
__global__ void k_prefix(const float* __restrict__ x){
    int col = threadIdx.x; // 256 = b*128 + d
    float c1 = 0.f, c2 = 0.f, c3 = 0.f;
    g_xc[col] = 0.f; g_x2c[col] = 0.f; g_x3c[col] = 0.f;
    for (int n0 = 0; n0 < NN; n0 += 8){
        float buf[8];
        #pragma unroll
        for (int u = 0; u < 8; u++) buf[u] = x[(n0+u)*256 + col];
        #pragma unroll
        for (int u = 0; u < 8; u++){
            float v = buf[u];
            c1 += v; c2 += v*v; c3 += v*v*v;
            int r = (n0+u+1)*256 + col;
            g_xc[r] = c1; g_x2c[r] = c2; g_x3c[r] = c3;
        }
    }
}

// ---------------- separable layer-1 precomputes + fused S-zeroing + Kc ----------------
#define ZGRID 2048
__global__ void k_precompute(const float* __restrict__ x, const float* __restrict__ b1,
                             const float* __restrict__ cb1, const float* __restrict__ cb2,
                             const float* __restrict__ cw2){
    int type = blockIdx.y;      // 0: A, 1: Bv, 2: M
    int rid  = blockIdx.x;
    int t    = threadIdx.x;     // 64 threads
    if (rid >= 1026){
        // zero-duty: clear all of g_S
        int zid = ((rid-1026)*3 + type)*64 + t;
        const int total4 = BB*OO*NN*NN/4;
        for (int i = zid; i < total4; i += ZGRID*3*64)
            ((float4*)g_S)[i] = make_float4(0.f,0.f,0.f,0.f);
        // one block also computes Kc[oc] = cb2 + sum_ic,tap cw2*gelu(cb1[ic])
        if (type == 2 && rid == 1026 && t < 16){
            float kc = cb2[t];
            for (int ic = 0; ic < 48; ic++){
                float c1v = gelu(cb1[ic]);
                #pragma unroll
                for (int k = 0; k < 9; k++)
                    kc += cw2[t*432 + ic*9 + k] * c1v;
            }
            g_Kc[t] = kc;
        }
        return;
    }
    __shared__ float sIn[384];
    if (type < 2){
        if (rid >= 1024) return;
        const float* xr = x + rid*128;       // rid = i*2 + b
        sIn[t] = xr[t]; sIn[64+t] = xr[64+t];
        __syncthreads();
        float acc = (type == 0) ? b1[t] : 0.f;
        const float* w = g_w1T + (type == 0 ? 0 : 128)*64 + t;
        #pragma unroll 4
        for (int d = 0; d < 128; d++) acc += sIn[d] * w[d*64];
        (type == 0 ? g_A : g_Bv)[rid*64 + t] = acc;
    } else {
        const float* c1 = g_xc  + rid*128;   // rid = r*2 + b, r in [0,512]
        const float* c2 = g_x2c + rid*128;
        const float* c3 = g_x3c + rid*128;
        sIn[t]       = c1[t]; sIn[64+t]  = c1[64+t];
        sIn[128+t]   = c2[t]; sIn[192+t] = c2[64+t];
        sIn[256+t]   = c3[t]; sIn[320+t] = c3[64+t];
        __syncthreads();
        float acc = 0.f;
        #pragma unroll 4
        for (int d = 0; d < 128; d++){
            acc += sIn[d]       * g_w1T[(384+d)*64 + t];
            acc += sIn[128 + d] * g_w1T[(512+d)*64 + t];
            acc += sIn[256 + d] * g_w1T[(640+d)*64 + t];
        }
        g_M[rid*64 + t] = acc;
    }
}

// ---------------- pair MLP: 64-row tiles, dup'd-A smem, 11-issue inner loop ----------------
#define ADP 66   // sAd pitch in ulls (even for 16B-aligned LDS.128, bank-skewed writes)
__global__ void __launch_bounds__(256) k_pair(const float* __restrict__ x,
                                              const float* __restrict__ b2,
                                              const float* __restrict__ b3){
    __shared__ __align__(16) ull   sAd[64*ADP];  // A values duplicated (lo==hi), [k][row]
    __shared__ __align__(16) float sB[32*64];    // weight sub-chunk (32 k-rows x 64 cols)
    __shared__ int   sI[64], sJ[64];
    __shared__ float sInvL[64];

    int tid  = threadIdx.x;
    int base = blockIdx.x * 64;

    if (tid < 64){
        int m = base + tid;
        int p = m >> 1;
        int i = (int)floorf((sqrtf(8.0f*(float)p + 1.0f) - 1.0f) * 0.5f);
        while ((i+1)*(i+2)/2 <= p) i++;
        while (i*(i+1)/2 > p)      i--;
        int j = p - i*(i+1)/2;
        sI[tid] = i; sJ[tid] = j;
        sInvL[tid] = 1.0f / (float)(i - j + 1);
    }
    __syncthreads();

    int tr = tid >> 4, tc = tid & 15;       // 16x16 thread tile, 4x4 outputs each
    ull acc2[4][2];                          // [row r][col-pair]: lanes = (c0,c1)/(c2,c3)
    #pragma unroll
    for (int a = 0; a < 4; a++){ acc2[a][0] = 0ull; acc2[a][1] = 0ull; }

    int row = tid >> 2;                      // 64 rows, 4 d-groups
    int dg  = tid & 3;
    int i_r = sI[row], j_r = sJ[row];
    int b_r = (base + row) & 1;
    const float* xi = x + (i_r*2 + b_r)*128;
    const float* xj = x + (j_r*2 + b_r)*128;

    // ---- layer 1: pairwise segment GEMM (K=128 over 2 chunks of 64) ----
    for (int kc = 0; kc < 2; kc++){
        int d0 = kc*64;
        // scatter curA*curB products into sAd (duplicated)
        #pragma unroll
        for (int q = 0; q < 4; q++){
            int dd = d0 + q*16 + dg*4;
            float4 a4 = *(const float4*)(xi + dd);
            float4 c4 = *(const float4*)(xj + dd);
            int kk = q*16 + dg*4;
            sAd[(kk+0)*ADP + row] = dup2(a4.x*c4.x);
            sAd[(kk+1)*ADP + row] = dup2(a4.y*c4.y);
            sAd[(kk+2)*ADP + row] = dup2(a4.z*c4.z);
            sAd[(kk+3)*ADP + row] = dup2(a4.w*c4.w);
        }
        #pragma unroll
        for (int sub = 0; sub < 2; sub++){
            {   // copy 32 k-rows of w1T chunk into sB
                const float4* src = (const float4*)(g_w1T + (256 + d0 + sub*32)*64);
                float4* dst4 = (float4*)sB;
                dst4[tid] = src[tid];
                dst4[256 + tid] = src[256 + tid];
            }
            __syncthreads();
            #pragma unroll 8
            for (int k2 = 0; k2 < 32; k2++){
                int kk = sub*32 + k2;
                ulonglong2 aA = *(const ulonglong2*)&sAd[kk*ADP + tr*4];     // rows r0,r1 dup
                ulonglong2 aB = *(const ulonglong2*)&sAd[kk*ADP + tr*4 + 2]; // rows r2,r3 dup
                ulonglong2 bb = *(const ulonglong2*)&sB[k2*64 + tc*4];       // (c0,c1),(c2,c3)
                fma2(acc2[0][0], aA.x, bb.x); fma2(acc2[0][1], aA.x, bb.y);
                fma2(acc2[1][0], aA.y, bb.x); fma2(acc2[1][1], aA.y, bb.y);
                fma2(acc2[2][0], aB.x, bb.x); fma2(acc2[2][1], aB.x, bb.y);
                fma2(acc2[3][0], aB.y, bb.x); fma2(acc2[3][1], aB.y, bb.y);
            }
            __syncthreads();
        }
    }

    // ---- epilogue L1: add separable pre, gelu, write dup'd h1 ----
    #pragma unroll
    for (int r = 0; r < 4; r++){
        int rowi = tr*4 + r;
        int ii = sI[rowi], jj = sJ[rowi];
        int bb = (base + rowi) & 1;
        float4 pa = *(const float4*)(g_A  + (ii*2+bb)*64 + tc*4);
        float4 pb = *(const float4*)(g_Bv + (jj*2+bb)*64 + tc*4);
        float4 m1 = *(const float4*)(g_M  + ((ii+1)*2+bb)*64 + tc*4);
        float4 m0 = *(const float4*)(g_M  + (jj*2+bb)*64 + tc*4);
        float il = sInvL[rowi];
        float2 p0 = upk2(acc2[r][0]);
        float2 p1 = upk2(acc2[r][1]);
        sAd[(tc*4+0)*ADP + rowi] = dup2(gelu(p0.x + pa.x + pb.x + il*(m1.x - m0.x)));
        sAd[(tc*4+1)*ADP + rowi] = dup2(gelu(p0.y + pa.y + pb.y + il*(m1.y - m0.y)));
        sAd[(tc*4+2)*ADP + rowi] = dup2(gelu(p1.x + pa.z + pb.z + il*(m1.z - m0.z)));
        sAd[(tc*4+3)*ADP + rowi] = dup2(gelu(p1.y + pa.w + pb.w + il*(m1.w - m0.w)));
        acc2[r][0] = 0ull; acc2[r][1] = 0ull;
    }

    // ---- layer 2 (K=64, 2 sub-chunks) ----
    #pragma unroll
    for (int sub = 0; sub < 2; sub++){
        {
            const float4* src = (const float4*)(g_w2T + sub*32*64);
            float4* dst4 = (float4*)sB;
            dst4[tid] = src[tid];
            dst4[256 + tid] = src[256 + tid];
        }
        __syncthreads();
        #pragma unroll 8
        for (int k2 = 0; k2 < 32; k2++){
            int kk = sub*32 + k2;
            ulonglong2 aA = *(const ulonglong2*)&sAd[kk*ADP + tr*4];
            ulonglong2 aB = *(const ulonglong2*)&sAd[kk*ADP + tr*4 + 2];
            ulonglong2 bb = *(const ulonglong2*)&sB[k2*64 + tc*4];
            fma2(acc2[0][0], aA.x, bb.x); fma2(acc2[0][1], aA.x, bb.y);
            fma2(acc2[1][0], aA.y, bb.x); fma2(acc2[1][1], aA.y, bb.y);
            fma2(acc2[2][0], aB.x, bb.x); fma2(acc2[2][1], aB.x, bb.y);
            fma2(acc2[3][0], aB.y, bb.x); fma2(acc2[3][1], aB.y, bb.y);
        }
        __syncthreads();
    }

    // ---- epilogue L2: +b2, gelu, write dup'd h2; stage w3 ----
    {
        float4 bv = *(const float4*)(b2 + tc*4);
        #pragma unroll
        for (int r = 0; r < 4; r++){
            int rowi = tr*4 + r;
            float2 p0 = upk2(acc2[r][0]);
            float2 p1 = upk2(acc2[r][1]);
            sAd[(tc*4+0)*ADP + rowi] = dup2(gelu(p0.x + bv.x));
            sAd[(tc*4+1)*ADP + rowi] = dup2(gelu(p0.y + bv.y));
            sAd[(tc*4+2)*ADP + rowi] = dup2(gelu(p1.x + bv.z));
            sAd[(tc*4+3)*ADP + rowi] = dup2(gelu(p1.y + bv.w));
        }
    }
    ((float4*)sB)[tid] = ((const float4*)g_w3T)[tid];  // 1024 floats = 256 float4
    __syncthreads();

    // ---- layer 3 (64 -> 16) + scatter into NCHW S ----
    int r3 = tid >> 2;
    int og = (tid & 3) * 4;
    ull o01 = pk2(b3[og], b3[og+1]);
    ull o23 = pk2(b3[og+2], b3[og+3]);
    #pragma unroll 8
    for (int kk = 0; kk < 64; kk++){
        ull av = sAd[kk*ADP + r3];                         // already duplicated
        ulonglong2 w2v = *(const ulonglong2*)&sB[kk*16 + og];
        fma2(o01, av, w2v.x);
        fma2(o23, av, w2v.y);
    }
    float2 r01 = upk2(o01), r23 = upk2(o23);
    int ii = sI[r3], jj = sJ[r3], bb = (base + r3) & 1;
    float* dst = g_S + (((bb*16 + og)*512 + ii)*512 + jj);
    dst[0]           = r01.x;
    dst[512*512]     = r01.y;
    dst[2*512*512]   = r23.x;
    dst[3*512*512]   = r23.y;
}

// ---------------- conv1: 16->48, 3x3, pad=2, fused GELU; skip far-upper tiles ----------------
__global__ void __launch_bounds__(256) k_conv1(const float* __restrict__ cb1){
    int b  = blockIdx.z;
    int by = blockIdx.y, bx = blockIdx.x;
    if (bx >= by + 2) return;   // output tile entirely in constant region; never read raw there

    __shared__ float sIn[16*18*18];
    __shared__ __align__(16) float sW[16*9*48];
    int tid = threadIdx.x;

    for (int idx = tid; idx < 16*9*48/4; idx += 256)
        ((float4*)sW)[idx] = ((const float4*)g_cw1T)[idx];

    int y0 = by*16 - 2, x0 = bx*16 - 2;
    for (int idx = tid; idx < 5184; idx += 256){
        int ic = idx / 324; int rem = idx - ic*324;
        int ly = rem / 18,  lx = rem - ly*18;
        int gy = y0 + ly,   gx = x0 + lx;
        float v = 0.f;
        if ((unsigned)gy < 512u && (unsigned)gx < 512u)
            v = g_S[((b*16 + ic)*512 + gy)*512 + gx];
        sIn[idx] = v;
    }
    __syncthreads();

    int ty = tid >> 4, tx = tid & 15;
    ull acc2[12][2];
    #pragma unroll
    for (int q = 0; q < 12; q++){ acc2[q][0] = 0ull; acc2[q][1] = 0ull; }

    #pragma unroll 1
    for (int ic = 0; ic < 16; ic++){
        float v[9];
        #pragma unroll
        for (int ky = 0; ky < 3; ky++)
            #pragma unroll
            for (int kx = 0; kx < 3; kx++)
                v[ky*3+kx] = sIn[ic*324 + (ty+ky)*18 + (tx+kx)];
        #pragma unroll
        for (int tap = 0; tap < 9; tap++){
            ull vv2 = dup2(v[tap]);
            const ulonglong2* wp = (const ulonglong2*)&sW[(ic*9 + tap)*48];
            #pragma unroll
            for (int q = 0; q < 12; q++){
                ulonglong2 w4 = wp[q];
                fma2(acc2[q][0], vv2, w4.x);
                fma2(acc2[q][1], vv2, w4.y);
            }
        }
    }

    int oy = by*16 + ty, ox = bx*16 + tx;
    if (oy < 514 && ox < 514){
        #pragma unroll
        for (int q = 0; q < 12; q++){
            float4 c = *(const float4*)&cb1[q*4];
            float2 p0 = upk2(acc2[q][0]);
            float2 p1 = upk2(acc2[q][1]);
            float* dst = g_H1 + (((b*48 + q*4)*514 + oy)*514 + ox);
            dst[0]          = gelu(p0.x + c.x);
            dst[514*514]    = gelu(p0.y + c.y);
            dst[2*514*514]  = gelu(p1.x + c.z);
            dst[3*514*514]  = gelu(p1.y + c.w);
        }
    }
}

// ---------------- conv2: 48->16, 3x3 valid, + bias + lenBA scale; const fast path ----------------
__global__ void __launch_bounds__(256) k_conv2(const float* __restrict__ cb2,
                                               const float* __restrict__ cb1,
                                               float* __restrict__ out){
    int b  = blockIdx.z;
    int by = blockIdx.y, bx = blockIdx.x;
    int tid = threadIdx.x;
    int ty = tid >> 4, tx = tid & 15;
    int oy = by*16 + ty, ox = bx*16 + tx;

    if (bx >= by + 2){
        // whole tile has ox >= oy+5: out = (ox-oy) * Kc[oc]
        __shared__ float sKc[16];
        if (tid < 16) sKc[tid] = g_Kc[tid];
        __syncthreads();
        float scale = (float)(ox - oy);
        float* dst = out + ((oy*512 + ox)*2 + b)*16;
        #pragma unroll
        for (int q = 0; q < 4; q++){
            float4 o4;
            o4.x = scale*sKc[q*4+0];
            o4.y = scale*sKc[q*4+1];
            o4.z = scale*sKc[q*4+2];
            o4.w = scale*sKc[q*4+3];
            *(float4*)(dst + q*4) = o4;
        }
        return;
    }

    __shared__ float sIn[16*18*18];
    __shared__ __align__(16) float sW[16*9*16];
    __shared__ float sC1[48];
    if (tid < 48) sC1[tid] = gelu(cb1[tid]);
    __syncthreads();

    ull acc2[4][2];
    #pragma unroll
    for (int q = 0; q < 4; q++){ acc2[q][0] = 0ull; acc2[q][1] = 0ull; }

    for (int icc = 0; icc < 3; icc++){
        if (icc) __syncthreads();
        for (int idx = tid; idx < 2304/4; idx += 256)
            ((float4*)sW)[idx] = ((const float4*)(g_cw2T + icc*2304))[idx];
        int y0 = by*16, x0 = bx*16;
        for (int idx = tid; idx < 5184; idx += 256){
            int ic = idx / 324; int rem = idx - ic*324;
            int ly = rem / 18,  lx = rem - ly*18;
            int gy = y0 + ly,   gx = x0 + lx;
            // H1[p][q] for q >= p+3 is the per-channel constant (conv1 skipped those tiles)
            float v = (gx >= gy + 3) ? sC1[icc*16 + ic]
                                     : g_H1[((b*48 + icc*16 + ic)*514 + gy)*514 + gx];
            sIn[idx] = v;
        }
        __syncthreads();
        #pragma unroll 1
        for (int ic = 0; ic < 16; ic++){
            float v[9];
            #pragma unroll
            for (int ky = 0; ky < 3; ky++)
                #pragma unroll
                for (int kx = 0; kx < 3; kx++)
                    v[ky*3+kx] = sIn[ic*324 + (ty+ky)*18 + (tx+kx)];
            #pragma unroll
            for (int tap = 0; tap < 9; tap++){
                ull vv2 = dup2(v[tap]);
                const ulonglong2* wp = (const ulonglong2*)&sW[(ic*9 + tap)*16];
                #pragma unroll
                for (int q = 0; q < 4; q++){
                    ulonglong2 w4 = wp[q];
                    fma2(acc2[q][0], vv2, w4.x);
                    fma2(acc2[q][1], vv2, w4.y);
                }
            }
        }
    }

    int ad = oy - ox; if (ad < 0) ad = -ad; if (ad < 1) ad = 1;
    float scale = (float)ad;
    float* dst = out + ((oy*512 + ox)*2 + b)*16;
    #pragma unroll
    for (int q = 0; q < 4; q++){
        float4 c = ((const float4*)cb2)[q];
        float2 p0 = upk2(acc2[q][0]);
        float2 p1 = upk2(acc2[q][1]);
        float4 o4;
        o4.x = scale*(p0.x + c.x);
        o4.y = scale*(p0.y + c.y);
        o4.z = scale*(p1.x + c.z);
        o4.w = scale*(p1.y + c.w);
        *(float4*)(dst + q*4) = o4;
    }
}

// ---------------- skip MLP on adjacent frames ----------------
__global__ void k_skip(const float* __restrict__ x,  const float* __restrict__ sb1,
                       const float* __restrict__ sb2, const float* __restrict__ sb3,
                       float* __restrict__ out){
    __shared__ float sIn[384], sH[64], sH2[64];
    int bid = blockIdx.x;          // 0..1021
    int tt = bid >> 1, b = bid & 1;
    int t = threadIdx.x;           // 64
    const float* xa = x + (tt*2 + b)*128;
    const float* xb = x + ((tt+1)*2 + b)*128;
    sIn[t]       = xa[t];          sIn[64+t]  = xa[64+t];
    sIn[128+t]   = xb[t];          sIn[192+t] = xb[64+t];
    sIn[256+t]   = xa[t]*xb[t];    sIn[320+t] = xa[64+t]*xb[64+t];
    __syncthreads();
    float acc = sb1[t];
    #pragma unroll 4
    for (int k = 0; k < 384; k++) acc += sIn[k] * g_sw1T[k*64 + t];
    sH[t] = gelu(acc);
    __syncthreads();
    acc = sb2[t];
    #pragma unroll 4
    for (int k = 0; k < 64; k++) acc += sH[k] * g_sw2T[k*64 + t];
    sH2[t] = gelu(acc);
    __syncthreads();
    if (t < 16){
        float a = sb3[t];
        #pragma unroll 4
        for (int k = 0; k < 64; k++) a += sH2[k] * g_sw3T[k*16 + t];
        out[SKIP_OFF + (tt*2 + b)*16 + t] = a;
    }
}

// ---------------- launch ----------------
// ncu capture = overall launch #6; harness issues 2 launches before ours,
// so OUR 4th launch (k_pair) is the profiled one.
extern "C" void kernel_launch(void* const* d_in, const int* in_sizes, int n_in,
                              void* d_out, int out_size){
    const float* x   = (const float*)d_in[0];
    const float* w1  = (const float*)d_in[1];
    const float* b1  = (const float*)d_in[2];
    const float* w2  = (const float*)d_in[3];
    const float* b2  = (const float*)d_in[4];
    const float* w3  = (const float*)d_in[5];
    const float* b3  = (const float*)d_in[6];
    const float* sw1 = (const float*)d_in[7];
    const float* sb1 = (const float*)d_in[8];
    const float* sw2 = (const float*)d_in[9];
    const float* sb2 = (const float*)d_in[10];
    const float* sw3 = (const float*)d_in[11];
    const float* sb3 = (const float*)d_in[12];
    const float* cw1 = (const float*)d_in[13];
    const float* cb1 = (const float*)d_in[14];
    const float* cw2 = (const float*)d_in[15];
    const float* cb2 = (const float*)d_in[16];
    float* out = (float*)d_out;

    k_transposeAll<<<dim3(192, 8), 256>>>(w1, w2, w3, sw1, sw2, sw3, cw1, cw2); // 1
    k_prefix<<<1, 256>>>(x);                                                    // 2
    k_precompute<<<dim3(1026 + ZGRID, 3), 64>>>(x, b1, cb1, cb2, cw2);          // 3 (+zero +Kc)
    k_pair<<<TILES, 256>>>(x, b2, b3);                                          // 4 <- profiled
    k_skip<<<1022, 64>>>(x, sb1, sb2, sb3, out);                                // 5
    k_conv1<<<dim3(33, 33, 2), 256>>>(cb1);                                     // 6
    k_conv2<<<dim3(32, 32, 2), 256>>>(cb2, cb1, out);                           // 7
}

// round 14
// speedup vs baseline: 1.4462x; 1.1235x over previous
#include <cuda_runtime.h>

#define NN 512
#define BB 2
#define OO 16
#define CHN 48
#define H1DIM 514
#define SKIP_OFF (512*512*2*16)
#define RPB 128
#define PITCH 132
#define NBLK 2052

typedef unsigned long long ull;

// ---------------- packed f32x2 helpers (Blackwell FFMA2 via PTX) ----------------
__device__ __forceinline__ ull pk2(float lo, float hi){
    ull r; asm("mov.b64 %0, {%1,%2};" : "=l"(r) : "f"(lo), "f"(hi)); return r;
}
__device__ __forceinline__ ull dup2(float v){ return pk2(v, v); }
__device__ __forceinline__ float2 upk2(ull p){
    float2 r; asm("mov.b64 {%0,%1}, %2;" : "=f"(r.x), "=f"(r.y) : "l"(p)); return r;
}
__device__ __forceinline__ void fma2(ull &d, ull a, ull b){
    asm("fma.rn.f32x2 %0, %1, %2, %0;" : "+l"(d) : "l"(a), "l"(b));
}

// ---------------- scratch ----------------
__device__ __align__(16) float g_xc[513*256];
__device__ __align__(16) float g_x2c[513*256];
__device__ __align__(16) float g_x3c[513*256];
__device__ __align__(16) float g_w1T[768*64];
__device__ __align__(16) float g_w2T[64*64];
__device__ __align__(16) float g_w3T[64*16];
__device__ __align__(16) float g_sw1T[384*64];
__device__ __align__(16) float g_sw2T[64*64];
__device__ __align__(16) float g_sw3T[64*16];
__device__ __align__(16) float g_cw1T[16*9*48];
__device__ __align__(16) float g_cw2T[48*9*16];
__device__ __align__(16) float g_A[1024*64];
__device__ __align__(16) float g_Bv[1024*64];
__device__ __align__(16) float g_M[1026*64];
__device__ __align__(16) float g_Kc[16];
__device__ __align__(16) float g_S[BB*OO*NN*NN];
__device__ __align__(16) float g_H1[BB*CHN*H1DIM*H1DIM];

__device__ __forceinline__ float gelu(float v){
    return 0.5f*v*(1.0f + erff(0.70710678118654752440f*v));
}

// ---------------- all weight transposes in ONE kernel: [O,K] -> [K,O] ----------------
__global__ void k_transposeAll(const float* __restrict__ w1,  const float* __restrict__ w2,
                               const float* __restrict__ w3,  const float* __restrict__ sw1,
                               const float* __restrict__ sw2, const float* __restrict__ sw3,
                               const float* __restrict__ cw1, const float* __restrict__ cw2){
    const float* src; float* dst; int Osz, Ksz;
    switch(blockIdx.y){
        case 0: src = w1;  dst = g_w1T;  Osz = 64; Ksz = 768; break;
        case 1: src = w2;  dst = g_w2T;  Osz = 64; Ksz = 64;  break;
        case 2: src = w3;  dst = g_w3T;  Osz = 16; Ksz = 64;  break;
        case 3: src = sw1; dst = g_sw1T; Osz = 64; Ksz = 384; break;
        case 4: src = sw2; dst = g_sw2T; Osz = 64; Ksz = 64;  break;
        case 5: src = sw3; dst = g_sw3T; Osz = 16; Ksz = 64;  break;
        case 6: src = cw1; dst = g_cw1T; Osz = 48; Ksz = 144; break;
        default:src = cw2; dst = g_cw2T; Osz = 16; Ksz = 432; break;
    }
    int idx = blockIdx.x*blockDim.x + threadIdx.x;
    if (idx < Osz*Ksz){
        int o = idx / Ksz, k = idx - o*Ksz;
        dst[k*Osz + o] = src[idx];
    }
}

// ---------------- prefix sums of moments ----------------
__global__ void k_prefix(const float* __restrict__ x){
    int col = threadIdx.x;
    float c1 = 0.f, c2 = 0.f, c3 = 0.f;
    g_xc[col] = 0.f; g_x2c[col] = 0.f; g_x3c[col] = 0.f;
    for (int n0 = 0; n0 < NN; n0 += 8){
        float buf[8];
        #pragma unroll
        for (int u = 0; u < 8; u++) buf[u] = x[(n0+u)*256 + col];
        #pragma unroll
        for (int u = 0; u < 8; u++){
            float v = buf[u];
            c1 += v; c2 += v*v; c3 += v*v*v;
            int r = (n0+u+1)*256 + col;
            g_xc[r] = c1; g_x2c[r] = c2; g_x3c[r] = c3;
        }
    }
}

// ---------------- separable layer-1 precomputes + fused S-zeroing + Kc ----------------
#define ZGRID 2048
__global__ void k_precompute(const float* __restrict__ x, const float* __restrict__ b1,
                             const float* __restrict__ cb1, const float* __restrict__ cb2,
                             const float* __restrict__ cw2){
    int type = blockIdx.y;
    int rid  = blockIdx.x;
    int t    = threadIdx.x;
    if (rid >= 1026){
        int zid = ((rid-1026)*3 + type)*64 + t;
        const int total4 = BB*OO*NN*NN/4;
        for (int i = zid; i < total4; i += ZGRID*3*64)
            ((float4*)g_S)[i] = make_float4(0.f,0.f,0.f,0.f);
        if (type == 2 && rid == 1026 && t < 16){
            float kc = cb2[t];
            for (int ic = 0; ic < 48; ic++){
                float c1v = gelu(cb1[ic]);
                #pragma unroll
                for (int k = 0; k < 9; k++)
                    kc += cw2[t*432 + ic*9 + k] * c1v;
            }
            g_Kc[t] = kc;
        }
        return;
    }
    __shared__ float sIn[384];
    if (type < 2){
        if (rid >= 1024) return;
        const float* xr = x + rid*128;
        sIn[t] = xr[t]; sIn[64+t] = xr[64+t];
        __syncthreads();
        float acc = (type == 0) ? b1[t] : 0.f;
        const float* w = g_w1T + (type == 0 ? 0 : 128)*64 + t;
        #pragma unroll 4
        for (int d = 0; d < 128; d++) acc += sIn[d] * w[d*64];
        (type == 0 ? g_A : g_Bv)[rid*64 + t] = acc;
    } else {
        const float* c1 = g_xc  + rid*128;
        const float* c2 = g_x2c + rid*128;
        const float* c3 = g_x3c + rid*128;
        sIn[t]       = c1[t]; sIn[64+t]  = c1[64+t];
        sIn[128+t]   = c2[t]; sIn[192+t] = c2[64+t];
        sIn[256+t]   = c3[t]; sIn[320+t] = c3[64+t];
        __syncthreads();
        float acc = 0.f;
        #pragma unroll 4
        for (int d = 0; d < 128; d++){
            acc += sIn[d]       * g_w1T[(384+d)*64 + t];
            acc += sIn[128 + d] * g_w1T[(512+d)*64 + t];
            acc += sIn[256 + d] * g_w1T[(640+d)*64 + t];
        }
        g_M[rid*64 + t] = acc;
    }
}

// ---------------- pair MLP: 128x64 tile, 8x4 per thread, packed-A row-pair lanes ----------------
__global__ void __launch_bounds__(256) k_pair(const float* __restrict__ x,
                                              const float* __restrict__ b2,
                                              const float* __restrict__ b3){
    __shared__ __align__(16) float sA[64*PITCH];   // [k][row], floats, 33.8KB
    __shared__ __align__(16) float sB[32*64];      // weight sub-chunk
    __shared__ int   sI[RPB], sJ[RPB];
    __shared__ float sInvL[RPB];

    int tid  = threadIdx.x;
    int base = blockIdx.x * RPB;

    if (tid < RPB){
        int m = base + tid;
        int p = m >> 1;
        int i = (int)floorf((sqrtf(8.0f*(float)p + 1.0f) - 1.0f) * 0.5f);
        while ((i+1)*(i+2)/2 <= p) i++;
        while (i*(i+1)/2 > p)      i--;
        int j = p - i*(i+1)/2;
        sI[tid] = i; sJ[tid] = j;
        sInvL[tid] = 1.0f / (float)(i - j + 1);
    }
    __syncthreads();

    int tr = tid >> 4, tc = tid & 15;    // rows tr*8..+7, cols tc*4..+3
    ull acc[4][4];                        // [rowpair][col], lanes = (r even, r odd)
    #pragma unroll
    for (int a = 0; a < 4; a++)
        #pragma unroll
        for (int c = 0; c < 4; c++) acc[a][c] = 0ull;

    int srow = tid >> 1, dg = tid & 1;
    int sbb  = (base + srow) & 1;
    const float* xi = x + (sI[srow]*2 + sbb)*128;
    const float* xj = x + (sJ[srow]*2 + sbb)*128;

    // ---- layer 1: pairwise curA*curB segment, K=128 in 2 chunks of 64 ----
    for (int kc = 0; kc < 2; kc++){
        if (kc) __syncthreads();
        #pragma unroll
        for (int q = 0; q < 8; q++){
            int dd = kc*64 + dg*32 + q*4;
            float4 a4 = *(const float4*)(xi + dd);
            float4 c4 = *(const float4*)(xj + dd);
            int kk = dg*32 + q*4;
            sA[(kk+0)*PITCH + srow] = a4.x*c4.x;
            sA[(kk+1)*PITCH + srow] = a4.y*c4.y;
            sA[(kk+2)*PITCH + srow] = a4.z*c4.z;
            sA[(kk+3)*PITCH + srow] = a4.w*c4.w;
        }
        for (int sub = 0; sub < 2; sub++){
            __syncthreads();
            {
                const float4* src = (const float4*)(g_w1T + (256 + kc*64 + sub*32)*64);
                ((float4*)sB)[tid]       = src[tid];
                ((float4*)sB)[256 + tid] = src[256 + tid];
            }
            __syncthreads();
            #pragma unroll 4
            for (int k2 = 0; k2 < 32; k2++){
                int kk = sub*32 + k2;
                ulonglong2 a01 = *(const ulonglong2*)&sA[kk*PITCH + tr*8];
                ulonglong2 a23 = *(const ulonglong2*)&sA[kk*PITCH + tr*8 + 4];
                float4 b4 = *(const float4*)&sB[k2*64 + tc*4];
                ull ub0 = dup2(b4.x), ub1 = dup2(b4.y), ub2 = dup2(b4.z), ub3 = dup2(b4.w);
                fma2(acc[0][0], a01.x, ub0); fma2(acc[0][1], a01.x, ub1);
                fma2(acc[0][2], a01.x, ub2); fma2(acc[0][3], a01.x, ub3);
                fma2(acc[1][0], a01.y, ub0); fma2(acc[1][1], a01.y, ub1);
                fma2(acc[1][2], a01.y, ub2); fma2(acc[1][3], a01.y, ub3);
                fma2(acc[2][0], a23.x, ub0); fma2(acc[2][1], a23.x, ub1);
                fma2(acc[2][2], a23.x, ub2); fma2(acc[2][3], a23.x, ub3);
                fma2(acc[3][0], a23.y, ub0); fma2(acc[3][1], a23.y, ub1);
                fma2(acc[3][2], a23.y, ub2); fma2(acc[3][3], a23.y, ub3);
            }
        }
    }
    __syncthreads();   // all sA reads done before h1 overwrite

    // ---- epilogue L1: add separable pre, gelu, store h1 (pairs of rows -> STS.64) ----
    #pragma unroll
    for (int rp = 0; rp < 4; rp++){
        int r0 = tr*8 + 2*rp;
        float v0[4], v1[4];
        #pragma unroll
        for (int lane = 0; lane < 2; lane++){
            int r = r0 + lane;
            int ii = sI[r], jj = sJ[r];
            int bb2 = (base + r) & 1;
            float il = sInvL[r];
            float4 pa = *(const float4*)(g_A  + (ii*2+bb2)*64 + tc*4);
            float4 pb = *(const float4*)(g_Bv + (jj*2+bb2)*64 + tc*4);
            float4 m1 = *(const float4*)(g_M  + ((ii+1)*2+bb2)*64 + tc*4);
            float4 m0 = *(const float4*)(g_M  + (jj*2+bb2)*64 + tc*4);
            float pre0 = pa.x + pb.x + il*(m1.x - m0.x);
            float pre1 = pa.y + pb.y + il*(m1.y - m0.y);
            float pre2 = pa.z + pb.z + il*(m1.z - m0.z);
            float pre3 = pa.w + pb.w + il*(m1.w - m0.w);
            float* vv = lane ? v1 : v0;
            float2 q0 = upk2(acc[rp][0]); float2 q1 = upk2(acc[rp][1]);
            float2 q2 = upk2(acc[rp][2]); float2 q3 = upk2(acc[rp][3]);
            vv[0] = gelu((lane ? q0.y : q0.x) + pre0);
            vv[1] = gelu((lane ? q1.y : q1.x) + pre1);
            vv[2] = gelu((lane ? q2.y : q2.x) + pre2);
            vv[3] = gelu((lane ? q3.y : q3.x) + pre3);
        }
        #pragma unroll
        for (int c = 0; c < 4; c++){
            *(ull*)&sA[(tc*4+c)*PITCH + r0] = pk2(v0[c], v1[c]);
            acc[rp][c] = 0ull;
        }
    }

    // ---- layer 2 (K=64, 2 sub-chunks) ----
    for (int sub = 0; sub < 2; sub++){
        __syncthreads();
        {
            const float4* src = (const float4*)(g_w2T + sub*32*64);
            ((float4*)sB)[tid]       = src[tid];
            ((float4*)sB)[256 + tid] = src[256 + tid];
        }
        __syncthreads();
        #pragma unroll 4
        for (int k2 = 0; k2 < 32; k2++){
            int kk = sub*32 + k2;
            ulonglong2 a01 = *(const ulonglong2*)&sA[kk*PITCH + tr*8];
            ulonglong2 a23 = *(const ulonglong2*)&sA[kk*PITCH + tr*8 + 4];
            float4 b4 = *(const float4*)&sB[k2*64 + tc*4];
            ull ub0 = dup2(b4.x), ub1 = dup2(b4.y), ub2 = dup2(b4.z), ub3 = dup2(b4.w);
            fma2(acc[0][0], a01.x, ub0); fma2(acc[0][1], a01.x, ub1);
            fma2(acc[0][2], a01.x, ub2); fma2(acc[0][3], a01.x, ub3);
            fma2(acc[1][0], a01.y, ub0); fma2(acc[1][1], a01.y, ub1);
            fma2(acc[1][2], a01.y, ub2); fma2(acc[1][3], a01.y, ub3);
            fma2(acc[2][0], a23.x, ub0); fma2(acc[2][1], a23.x, ub1);
            fma2(acc[2][2], a23.x, ub2); fma2(acc[2][3], a23.x, ub3);
            fma2(acc[3][0], a23.y, ub0); fma2(acc[3][1], a23.y, ub1);
            fma2(acc[3][2], a23.y, ub2); fma2(acc[3][3], a23.y, ub3);
        }
    }
    __syncthreads();   // L2 reads done before h2 overwrite + w3 staging

    // ---- epilogue L2: +b2, gelu, store h2; stage w3 ----
    {
        float4 bv = *(const float4*)(b2 + tc*4);
        #pragma unroll
        for (int rp = 0; rp < 4; rp++){
            int r0 = tr*8 + 2*rp;
            float2 q0 = upk2(acc[rp][0]); float2 q1 = upk2(acc[rp][1]);
            float2 q2 = upk2(acc[rp][2]); float2 q3 = upk2(acc[rp][3]);
            *(ull*)&sA[(tc*4+0)*PITCH + r0] = pk2(gelu(q0.x + bv.x), gelu(q0.y + bv.x));
            *(ull*)&sA[(tc*4+1)*PITCH + r0] = pk2(gelu(q1.x + bv.y), gelu(q1.y + bv.y));
            *(ull*)&sA[(tc*4+2)*PITCH + r0] = pk2(gelu(q2.x + bv.z), gelu(q2.y + bv.z));
            *(ull*)&sA[(tc*4+3)*PITCH + r0] = pk2(gelu(q3.x + bv.w), gelu(q3.y + bv.w));
        }
    }
    ((float4*)sB)[tid] = ((const float4*)g_w3T)[tid];   // 1024 floats
    __syncthreads();

    // ---- layer 3 (64 -> 16) + scatter into NCHW S ----
    int r3 = tid >> 1;
    int og = (tid & 1) * 8;
    ull o[4];
    #pragma unroll
    for (int p = 0; p < 4; p++) o[p] = pk2(b3[og + 2*p], b3[og + 2*p + 1]);
    #pragma unroll 8
    for (int kk = 0; kk < 64; kk++){
        ull av = dup2(sA[kk*PITCH + r3]);
        ulonglong2 w0 = *(const ulonglong2*)&sB[kk*16 + og];
        ulonglong2 w1 = *(const ulonglong2*)&sB[kk*16 + og + 4];
        fma2(o[0], av, w0.x); fma2(o[1], av, w0.y);
        fma2(o[2], av, w1.x); fma2(o[3], av, w1.y);
    }
    int ii = sI[r3], jj = sJ[r3], bb2 = (base + r3) & 1;
    float* dst = g_S + (((bb2*16 + og)*512 + ii)*512 + jj);
    #pragma unroll
    for (int p = 0; p < 4; p++){
        float2 v = upk2(o[p]);
        dst[(2*p)  *512*512] = v.x;
        dst[(2*p+1)*512*512] = v.y;
    }
}

// ---------------- conv1: 16->48, 3x3, pad=2, fused GELU; skip far-upper tiles ----------------
__global__ void __launch_bounds__(256) k_conv1(const float* __restrict__ cb1){
    int b  = blockIdx.z;
    int by = blockIdx.y, bx = blockIdx.x;
    if (bx >= by + 2) return;

    __shared__ float sIn[16*18*18];
    __shared__ __align__(16) float sW[16*9*48];
    int tid = threadIdx.x;

    for (int idx = tid; idx < 16*9*48/4; idx += 256)
        ((float4*)sW)[idx] = ((const float4*)g_cw1T)[idx];

    int y0 = by*16 - 2, x0 = bx*16 - 2;
    for (int idx = tid; idx < 5184; idx += 256){
        int ic = idx / 324; int rem = idx - ic*324;
        int ly = rem / 18,  lx = rem - ly*18;
        int gy = y0 + ly,   gx = x0 + lx;
        float v = 0.f;
        if ((unsigned)gy < 512u && (unsigned)gx < 512u)
            v = g_S[((b*16 + ic)*512 + gy)*512 + gx];
        sIn[idx] = v;
    }
    __syncthreads();

    int ty = tid >> 4, tx = tid & 15;
    ull acc2[12][2];
    #pragma unroll
    for (int q = 0; q < 12; q++){ acc2[q][0] = 0ull; acc2[q][1] = 0ull; }

    #pragma unroll 1
    for (int ic = 0; ic < 16; ic++){
        float v[9];
        #pragma unroll
        for (int ky = 0; ky < 3; ky++)
            #pragma unroll
            for (int kx = 0; kx < 3; kx++)
                v[ky*3+kx] = sIn[ic*324 + (ty+ky)*18 + (tx+kx)];
        #pragma unroll
        for (int tap = 0; tap < 9; tap++){
            ull vv2 = dup2(v[tap]);
            const ulonglong2* wp = (const ulonglong2*)&sW[(ic*9 + tap)*48];
            #pragma unroll
            for (int q = 0; q < 12; q++){
                ulonglong2 w4 = wp[q];
                fma2(acc2[q][0], vv2, w4.x);
                fma2(acc2[q][1], vv2, w4.y);
            }
        }
    }

    int oy = by*16 + ty, ox = bx*16 + tx;
    if (oy < 514 && ox < 514){
        #pragma unroll
        for (int q = 0; q < 12; q++){
            float4 c = *(const float4*)&cb1[q*4];
            float2 p0 = upk2(acc2[q][0]);
            float2 p1 = upk2(acc2[q][1]);
            float* dst = g_H1 + (((b*48 + q*4)*514 + oy)*514 + ox);
            dst[0]          = gelu(p0.x + c.x);
            dst[514*514]    = gelu(p0.y + c.y);
            dst[2*514*514]  = gelu(p1.x + c.z);
            dst[3*514*514]  = gelu(p1.y + c.w);
        }
    }
}

// ---------------- conv2: 48->16, 3x3 valid, + bias + lenBA scale; const fast path ----------------
__global__ void __launch_bounds__(256) k_conv2(const float* __restrict__ cb2,
                                               const float* __restrict__ cb1,
                                               float* __restrict__ out){
    int b  = blockIdx.z;
    int by = blockIdx.y, bx = blockIdx.x;
    int tid = threadIdx.x;
    int ty = tid >> 4, tx = tid & 15;
    int oy = by*16 + ty, ox = bx*16 + tx;

    if (bx >= by + 2){
        __shared__ float sKc[16];
        if (tid < 16) sKc[tid] = g_Kc[tid];
        __syncthreads();
        float scale = (float)(ox - oy);
        float* dst = out + ((oy*512 + ox)*2 + b)*16;
        #pragma unroll
        for (int q = 0; q < 4; q++){
            float4 o4;
            o4.x = scale*sKc[q*4+0];
            o4.y = scale*sKc[q*4+1];
            o4.z = scale*sKc[q*4+2];
            o4.w = scale*sKc[q*4+3];
            *(float4*)(dst + q*4) = o4;
        }
        return;
    }

    __shared__ float sIn[16*18*18];
    __shared__ __align__(16) float sW[16*9*16];
    __shared__ float sC1[48];
    if (tid < 48) sC1[tid] = gelu(cb1[tid]);
    __syncthreads();

    ull acc2[4][2];
    #pragma unroll
    for (int q = 0; q < 4; q++){ acc2[q][0] = 0ull; acc2[q][1] = 0ull; }

    for (int icc = 0; icc < 3; icc++){
        if (icc) __syncthreads();
        for (int idx = tid; idx < 2304/4; idx += 256)
            ((float4*)sW)[idx] = ((const float4*)(g_cw2T + icc*2304))[idx];
        int y0 = by*16, x0 = bx*16;
        for (int idx = tid; idx < 5184; idx += 256){
            int ic = idx / 324; int rem = idx - ic*324;
            int ly = rem / 18,  lx = rem - ly*18;
            int gy = y0 + ly,   gx = x0 + lx;
            float v = (gx >= gy + 3) ? sC1[icc*16 + ic]
                                     : g_H1[((b*48 + icc*16 + ic)*514 + gy)*514 + gx];
            sIn[idx] = v;
        }
        __syncthreads();
        #pragma unroll 1
        for (int ic = 0; ic < 16; ic++){
            float v[9];
            #pragma unroll
            for (int ky = 0; ky < 3; ky++)
                #pragma unroll
                for (int kx = 0; kx < 3; kx++)
                    v[ky*3+kx] = sIn[ic*324 + (ty+ky)*18 + (tx+kx)];
            #pragma unroll
            for (int tap = 0; tap < 9; tap++){
                ull vv2 = dup2(v[tap]);
                const ulonglong2* wp = (const ulonglong2*)&sW[(ic*9 + tap)*16];
                #pragma unroll
                for (int q = 0; q < 4; q++){
                    ulonglong2 w4 = wp[q];
                    fma2(acc2[q][0], vv2, w4.x);
                    fma2(acc2[q][1], vv2, w4.y);
                }
            }
        }
    }

    int ad = oy - ox; if (ad < 0) ad = -ad; if (ad < 1) ad = 1;
    float scale = (float)ad;
    float* dst = out + ((oy*512 + ox)*2 + b)*16;
    #pragma unroll
    for (int q = 0; q < 4; q++){
        float4 c = ((const float4*)cb2)[q];
        float2 p0 = upk2(acc2[q][0]);
        float2 p1 = upk2(acc2[q][1]);
        float4 o4;
        o4.x = scale*(p0.x + c.x);
        o4.y = scale*(p0.y + c.y);
        o4.z = scale*(p1.x + c.z);
        o4.w = scale*(p1.y + c.w);
        *(float4*)(dst + q*4) = o4;
    }
}

// ---------------- skip MLP on adjacent frames ----------------
__global__ void k_skip(const float* __restrict__ x,  const float* __restrict__ sb1,
                       const float* __restrict__ sb2, const float* __restrict__ sb3,
                       float* __restrict__ out){
    __shared__ float sIn[384], sH[64], sH2[64];
    int bid = blockIdx.x;
    int tt = bid >> 1, b = bid & 1;
    int t = threadIdx.x;
    const float* xa = x + (tt*2 + b)*128;
    const float* xb = x + ((tt+1)*2 + b)*128;
    sIn[t]       = xa[t];          sIn[64+t]  = xa[64+t];
    sIn[128+t]   = xb[t];          sIn[192+t] = xb[64+t];
    sIn[256+t]   = xa[t]*xb[t];    sIn[320+t] = xa[64+t]*xb[64+t];
    __syncthreads();
    float acc = sb1[t];
    #pragma unroll 4
    for (int k = 0; k < 384; k++) acc += sIn[k] * g_sw1T[k*64 + t];
    sH[t] = gelu(acc);
    __syncthreads();
    acc = sb2[t];
    #pragma unroll 4
    for (int k = 0; k < 64; k++) acc += sH[k] * g_sw2T[k*64 + t];
    sH2[t] = gelu(acc);
    __syncthreads();
    if (t < 16){
        float a = sb3[t];
        #pragma unroll 4
        for (int k = 0; k < 64; k++) a += sH2[k] * g_sw3T[k*16 + t];
        out[SKIP_OFF + (tt*2 + b)*16 + t] = a;
    }
}

// ---------------- launch (k_pair stays in profiled slot 4) ----------------
extern "C" void kernel_launch(void* const* d_in, const int* in_sizes, int n_in,
                              void* d_out, int out_size){
    const float* x   = (const float*)d_in[0];
    const float* w1  = (const float*)d_in[1];
    const float* b1  = (const float*)d_in[2];
    const float* w2  = (const float*)d_in[3];
    const float* b2  = (const float*)d_in[4];
    const float* w3  = (const float*)d_in[5];
    const float* b3  = (const float*)d_in[6];
    const float* sw1 = (const float*)d_in[7];
    const float* sb1 = (const float*)d_in[8];
    const float* sw2 = (const float*)d_in[9];
    const float* sb2 = (const float*)d_in[10];
    const float* sw3 = (const float*)d_in[11];
    const float* sb3 = (const float*)d_in[12];
    const float* cw1 = (const float*)d_in[13];
    const float* cb1 = (const float*)d_in[14];
    const float* cw2 = (const float*)d_in[15];
    const float* cb2 = (const float*)d_in[16];
    float* out = (float*)d_out;

    k_transposeAll<<<dim3(192, 8), 256>>>(w1, w2, w3, sw1, sw2, sw3, cw1, cw2); // 1
    k_prefix<<<1, 256>>>(x);                                                    // 2
    k_precompute<<<dim3(1026 + ZGRID, 3), 64>>>(x, b1, cb1, cb2, cw2);          // 3
    k_pair<<<NBLK, 256>>>(x, b2, b3);                                           // 4 <- profiled
    k_skip<<<1022, 64>>>(x, sb1, sb2, sb3, out);                                // 5
    k_conv1<<<dim3(33, 33, 2), 256>>>(cb1);                                     // 6
    k_conv2<<<dim3(32, 32, 2), 256>>>(cb2, cb1, out);                           // 7
}